// round 2
// baseline (speedup 1.0000x reference)
#include <cuda_runtime.h>
#include <math.h>

// Problem constants
#define NN    10000          // nodes
#define EE    160000         // edges (without self loops)
#define EP    170000         // edges + self loops
#define HH    8              // heads (layers 1,2)
#define CC    64             // channels per head
#define HC    512            // H*C
#define GG    64             // graphs
#define NCLS  64             // classes

// ---------------- device scratch (static; no allocation) ----------------
__device__ float g_bufA[NN * HC];
__device__ float g_bufB[NN * HC];
__device__ float g_h[NN * HC];
__device__ float g_gat[NN * HC];
__device__ float g_ssrc[NN * HH];
__device__ float g_sdst[NN * HH];
__device__ float g_x3[NN * CC];
__device__ float g_gat3[NN * CC];
__device__ int   g_rowptr[NN + 1];
__device__ int   g_cnt[NN];
__device__ int   g_csrc[EP];
__device__ float g_bnsum[HC];
__device__ float g_bnsq[HC];
__device__ float g_scale[HC];
__device__ float g_shift[HC];
__device__ float g_pool[GG * CC];
__device__ float g_cntg[GG];

// ---------------- CSR build ----------------
__global__ void k_zero_cnt() {
    int i = blockIdx.x * blockDim.x + threadIdx.x;
    if (i < NN) g_cnt[i] = 0;
}

__global__ void k_count(const int* __restrict__ ei) {
    int e = blockIdx.x * blockDim.x + threadIdx.x;
    if (e < EE) atomicAdd(&g_cnt[ei[EE + e]], 1);
}

// exclusive scan of (cnt[i]+1) -> rowptr ; single block of 1024 threads
__global__ void k_scan() {
    __shared__ int sh[1024];
    __shared__ int carry;
    int tid = threadIdx.x;
    if (tid == 0) carry = 0;
    __syncthreads();
    for (int base = 0; base < NN; base += 1024) {
        int i = base + tid;
        int v = (i < NN) ? (g_cnt[i] + 1) : 0;   // +1 self loop
        sh[tid] = v;
        __syncthreads();
        for (int off = 1; off < 1024; off <<= 1) {
            int t = (tid >= off) ? sh[tid - off] : 0;
            __syncthreads();
            sh[tid] += t;
            __syncthreads();
        }
        if (i < NN) g_rowptr[i + 1] = carry + sh[tid];
        __syncthreads();
        if (tid == 1023) carry += sh[1023];
        __syncthreads();
    }
    if (tid == 0) g_rowptr[0] = 0;
}

__global__ void k_fill_self() {
    int i = blockIdx.x * blockDim.x + threadIdx.x;
    if (i < NN) {
        int rp = g_rowptr[i];
        g_csrc[rp] = i;          // self loop first
        g_cnt[i] = rp + 1;       // cursor
    }
}

__global__ void k_fill(const int* __restrict__ ei) {
    int e = blockIdx.x * blockDim.x + threadIdx.x;
    if (e < EE) {
        int dst = ei[EE + e];
        int slot = atomicAdd(&g_cnt[dst], 1);
        g_csrc[slot] = ei[e];
    }
}

// ---------------- GEMM: C[M,Nn] = A[M,K] @ B[K,Nn] (+ bias) ----------------
// 128x128x16 tile, 256 threads, 8x8 microtile
__global__ __launch_bounds__(256, 2)
void k_gemm(const float* __restrict__ A, const float* __restrict__ B,
            const float* __restrict__ bias, float* __restrict__ Cm,
            int M, int K, int Nn) {
    __shared__ float As[16][132];
    __shared__ float Bs[16][128];
    const int bm = blockIdx.y * 128;
    const int bn = blockIdx.x * 128;
    const int tid = threadIdx.x;
    const int tx = tid & 15, ty = tid >> 4;
    float acc[8][8];
#pragma unroll
    for (int i = 0; i < 8; i++)
#pragma unroll
        for (int j = 0; j < 8; j++) acc[i][j] = 0.f;

    for (int k0 = 0; k0 < K; k0 += 16) {
#pragma unroll
        for (int i = 0; i < 2; i++) {
            int idx = tid + i * 256;
            int r = idx >> 2, c4 = (idx & 3) << 2;
            int gr = bm + r;
            float4 v = make_float4(0.f, 0.f, 0.f, 0.f);
            if (gr < M) v = *(const float4*)(A + (size_t)gr * K + k0 + c4);
            As[c4 + 0][r] = v.x; As[c4 + 1][r] = v.y;
            As[c4 + 2][r] = v.z; As[c4 + 3][r] = v.w;
        }
#pragma unroll
        for (int i = 0; i < 2; i++) {
            int idx = tid + i * 256;
            int r = idx >> 5, cc = (idx & 31) << 2;
            int gc = bn + cc;
            float4 v = make_float4(0.f, 0.f, 0.f, 0.f);
            if (gc < Nn) v = *(const float4*)(B + (size_t)(k0 + r) * Nn + gc);
            *(float4*)&Bs[r][cc] = v;
        }
        __syncthreads();
#pragma unroll
        for (int k = 0; k < 16; k++) {
            float a[8], b[8];
            *(float4*)&a[0] = *(const float4*)&As[k][ty * 8];
            *(float4*)&a[4] = *(const float4*)&As[k][ty * 8 + 4];
            *(float4*)&b[0] = *(const float4*)&Bs[k][tx * 8];
            *(float4*)&b[4] = *(const float4*)&Bs[k][tx * 8 + 4];
#pragma unroll
            for (int i = 0; i < 8; i++)
#pragma unroll
                for (int j = 0; j < 8; j++)
                    acc[i][j] = fmaf(a[i], b[j], acc[i][j]);
        }
        __syncthreads();
    }
#pragma unroll
    for (int i = 0; i < 8; i++) {
        int gr = bm + ty * 8 + i;
        if (gr >= M) continue;
#pragma unroll
        for (int j = 0; j < 8; j += 4) {
            int gc = bn + tx * 8 + j;
            if (gc >= Nn) continue;
            float4 o;
            o.x = acc[i][j]; o.y = acc[i][j + 1];
            o.z = acc[i][j + 2]; o.w = acc[i][j + 3];
            if (bias) {
                o.x += bias[gc]; o.y += bias[gc + 1];
                o.z += bias[gc + 2]; o.w += bias[gc + 3];
            }
            *(float4*)(Cm + (size_t)gr * Nn + gc) = o;
        }
    }
}

// ---------------- attention score precompute: s = sum_c h[n,h,c]*a[h,c] ----------------
// blockDim = 32*H, one block per node, one warp per head
__global__ void k_scores(const float* __restrict__ h, const float* __restrict__ a_s,
                         const float* __restrict__ a_d, float* __restrict__ ssrc,
                         float* __restrict__ sdst, int Hh) {
    int n = blockIdx.x;
    int warp = threadIdx.x >> 5, lane = threadIdx.x & 31;
    const float* hp = h + (size_t)n * Hh * CC + warp * CC;
    float v0 = hp[lane], v1 = hp[lane + 32];
    float s1 = v0 * a_s[warp * CC + lane] + v1 * a_s[warp * CC + lane + 32];
    float s2 = v0 * a_d[warp * CC + lane] + v1 * a_d[warp * CC + lane + 32];
#pragma unroll
    for (int o = 16; o >= 1; o >>= 1) {
        s1 += __shfl_xor_sync(0xffffffffu, s1, o);
        s2 += __shfl_xor_sync(0xffffffffu, s2, o);
    }
    if (lane == 0) { ssrc[n * Hh + warp] = s1; sdst[n * Hh + warp] = s2; }
}

__device__ __forceinline__ float lrelu02(float x) { return x > 0.f ? x : 0.2f * x; }

// ---------------- GAT aggregation, H=8: one block of 128 per dst ----------------
__global__ void k_agg8(const float* __restrict__ hbuf, const float* __restrict__ ssrc,
                       const float* __restrict__ sdst, const float* __restrict__ bias,
                       float* __restrict__ out) {
    int dstn = blockIdx.x;
    int tid = threadIdx.x;
    __shared__ float sh_sdst[HH], sh_m[HH], sh_s[HH];
    if (tid < HH) sh_sdst[tid] = sdst[dstn * HH + tid];
    __syncthreads();
    int beg = g_rowptr[dstn], end = g_rowptr[dstn + 1];
    int warp = tid >> 5, lane = tid & 31;
    {
        int hh = warp * 2 + (lane >> 4);
        int sub = lane & 15;
        float sd = sh_sdst[hh];
        float mx = -3.4e38f;
        for (int i = beg + sub; i < end; i += 16)
            mx = fmaxf(mx, lrelu02(ssrc[g_csrc[i] * HH + hh] + sd));
#pragma unroll
        for (int o = 1; o < 16; o <<= 1) mx = fmaxf(mx, __shfl_xor_sync(0xffffffffu, mx, o));
        float se = 0.f;
        for (int i = beg + sub; i < end; i += 16)
            se += __expf(lrelu02(ssrc[g_csrc[i] * HH + hh] + sd) - mx);
#pragma unroll
        for (int o = 1; o < 16; o <<= 1) se += __shfl_xor_sync(0xffffffffu, se, o);
        if (sub == 0) { sh_m[hh] = mx; sh_s[hh] = se; }
    }
    __syncthreads();
    int hh = tid >> 4;
    int c4 = (tid & 15) << 2;
    float m = sh_m[hh];
    float sinv = 1.f / (sh_s[hh] + 1e-16f);
    float sd = sh_sdst[hh];
    float4 acc = make_float4(0.f, 0.f, 0.f, 0.f);
    for (int i = beg; i < end; i++) {
        int s = g_csrc[i];
        float alpha = __expf(lrelu02(ssrc[s * HH + hh] + sd) - m) * sinv;
        float4 v = *(const float4*)(hbuf + (size_t)s * HC + hh * CC + c4);
        acc.x = fmaf(alpha, v.x, acc.x);
        acc.y = fmaf(alpha, v.y, acc.y);
        acc.z = fmaf(alpha, v.z, acc.z);
        acc.w = fmaf(alpha, v.w, acc.w);
    }
    float4 bb = *(const float4*)(bias + hh * CC + c4);
    acc.x += bb.x; acc.y += bb.y; acc.z += bb.z; acc.w += bb.w;
    *(float4*)(out + (size_t)dstn * HC + hh * CC + c4) = acc;
}

// ---------------- GAT aggregation, H=1 C=64: 64 threads per dst ----------------
__global__ void k_agg1(const float* __restrict__ h3, const float* __restrict__ ssrc,
                       const float* __restrict__ sdst, const float* __restrict__ bias,
                       float* __restrict__ out) {
    int dstn = blockIdx.x;
    int tid = threadIdx.x;
    __shared__ float sh_m, sh_s;
    float sd = sdst[dstn];
    int beg = g_rowptr[dstn], end = g_rowptr[dstn + 1];
    if (tid < 32) {
        float mx = -3.4e38f;
        for (int i = beg + tid; i < end; i += 32)
            mx = fmaxf(mx, lrelu02(ssrc[g_csrc[i]] + sd));
#pragma unroll
        for (int o = 1; o < 32; o <<= 1) mx = fmaxf(mx, __shfl_xor_sync(0xffffffffu, mx, o));
        float se = 0.f;
        for (int i = beg + tid; i < end; i += 32)
            se += __expf(lrelu02(ssrc[g_csrc[i]] + sd) - mx);
#pragma unroll
        for (int o = 1; o < 32; o <<= 1) se += __shfl_xor_sync(0xffffffffu, se, o);
        if (tid == 0) { sh_m = mx; sh_s = se; }
    }
    __syncthreads();
    float m = sh_m;
    float sinv = 1.f / (sh_s + 1e-16f);
    float acc = 0.f;
    for (int i = beg; i < end; i++) {
        int s = g_csrc[i];
        float alpha = __expf(lrelu02(ssrc[s] + sd) - m) * sinv;
        acc = fmaf(alpha, h3[(size_t)s * CC + tid], acc);
    }
    out[(size_t)dstn * CC + tid] = acc + bias[tid];
}

// ---------------- BatchNorm (training stats) ----------------
__global__ void k_bnzero(int Cdim) {
    int c = threadIdx.x;
    if (c < Cdim) { g_bnsum[c] = 0.f; g_bnsq[c] = 0.f; }
}

__global__ void k_bnstats(const float* __restrict__ x, int Cdim, int rowsPerBlock) {
    int c = threadIdx.x;
    int r0 = blockIdx.x * rowsPerBlock;
    int r1 = min(r0 + rowsPerBlock, NN);
    float s = 0.f, q = 0.f;
    for (int r = r0; r < r1; r++) {
        float v = x[(size_t)r * Cdim + c];
        s += v; q = fmaf(v, v, q);
    }
    atomicAdd(&g_bnsum[c], s);
    atomicAdd(&g_bnsq[c], q);
}

__global__ void k_bnfinal(const float* __restrict__ g, const float* __restrict__ be, int Cdim) {
    int c = threadIdx.x;
    if (c >= Cdim) return;
    float mu = g_bnsum[c] / (float)NN;
    float var = g_bnsq[c] / (float)NN - mu * mu;
    var = fmaxf(var, 0.f);
    float inv = rsqrtf(var + 1e-5f);
    float sc = g[c] * inv;
    g_scale[c] = sc;
    g_shift[c] = be[c] - sc * mu;
}

// out = (res? res : 0) + (doElu ? elu(scale*in+shift) : scale*in+shift)
__global__ void k_bnapply(const float* __restrict__ in, const float* __restrict__ res,
                          float* __restrict__ out, int Cdim, int doElu, int total4) {
    int i = blockIdx.x * blockDim.x + threadIdx.x;
    int stride = gridDim.x * blockDim.x;
    int c4cnt = Cdim >> 2;
    for (; i < total4; i += stride) {
        int c4 = (i % c4cnt) << 2;
        float4 v = ((const float4*)in)[i];
        float4 sc = *(const float4*)&g_scale[c4];
        float4 sh = *(const float4*)&g_shift[c4];
        float o0 = fmaf(sc.x, v.x, sh.x);
        float o1 = fmaf(sc.y, v.y, sh.y);
        float o2 = fmaf(sc.z, v.z, sh.z);
        float o3 = fmaf(sc.w, v.w, sh.w);
        if (doElu) {
            o0 = o0 > 0.f ? o0 : expm1f(o0);
            o1 = o1 > 0.f ? o1 : expm1f(o1);
            o2 = o2 > 0.f ? o2 : expm1f(o2);
            o3 = o3 > 0.f ? o3 : expm1f(o3);
        }
        if (res) {
            float4 rv = ((const float4*)res)[i];
            o0 += rv.x; o1 += rv.y; o2 += rv.z; o3 += rv.w;
        }
        float4 o; o.x = o0; o.y = o1; o.z = o2; o.w = o3;
        ((float4*)out)[i] = o;
    }
}

// ---------------- pooling + classifier ----------------
__global__ void k_poolzero() {
    int i = threadIdx.x + blockIdx.x * blockDim.x;
    if (i < GG * CC) g_pool[i] = 0.f;
    if (i < GG) g_cntg[i] = 0.f;
}

__global__ void k_pool(const float* __restrict__ x3, const int* __restrict__ batch) {
    int n = blockIdx.x;
    int c = threadIdx.x;
    int g = batch[n];
    atomicAdd(&g_pool[g * CC + c], x3[(size_t)n * CC + c]);
    if (c == 0) atomicAdd(&g_cntg[g], 1.0f);
}

__global__ void k_final(const float* __restrict__ linW, const float* __restrict__ linb,
                        float* __restrict__ out) {
    int g = blockIdx.x;
    int j = threadIdx.x;
    __shared__ float xg[CC];
    float cv = fmaxf(g_cntg[g], 1.0f);
    xg[j] = g_pool[g * CC + j] / cv;
    __syncthreads();
    float acc = linb[j];
#pragma unroll
    for (int c = 0; c < CC; c++) acc = fmaf(xg[c], linW[c * NCLS + j], acc);
    out[g * NCLS + j] = acc;
}

// ---------------- host side ----------------
extern "C" void kernel_launch(void* const* d_in, const int* in_sizes, int n_in,
                              void* d_out, int out_size) {
    const float* x      = (const float*)d_in[0];
    const int*   ei     = (const int*)d_in[1];
    const int*   batch  = (const int*)d_in[2];
    const float* enc_W  = (const float*)d_in[3];
    const float* enc_b  = (const float*)d_in[4];
    const float* W1     = (const float*)d_in[5];
    const float* as1    = (const float*)d_in[6];
    const float* ad1    = (const float*)d_in[7];
    const float* b1     = (const float*)d_in[8];
    const float* g1     = (const float*)d_in[9];
    const float* be1    = (const float*)d_in[10];
    const float* W2     = (const float*)d_in[11];
    const float* as2    = (const float*)d_in[12];
    const float* ad2    = (const float*)d_in[13];
    const float* b2     = (const float*)d_in[14];
    const float* g2     = (const float*)d_in[15];
    const float* be2    = (const float*)d_in[16];
    const float* W3     = (const float*)d_in[17];
    const float* as3    = (const float*)d_in[18];
    const float* ad3    = (const float*)d_in[19];
    const float* b3     = (const float*)d_in[20];
    const float* g3     = (const float*)d_in[21];
    const float* be3    = (const float*)d_in[22];
    const float* linW   = (const float*)d_in[23];
    const float* linb   = (const float*)d_in[24];
    float* out = (float*)d_out;

    float *bufA, *bufB, *hbuf, *gat, *ssrc, *sdst, *x3, *gat3;
    cudaGetSymbolAddress((void**)&bufA, g_bufA);
    cudaGetSymbolAddress((void**)&bufB, g_bufB);
    cudaGetSymbolAddress((void**)&hbuf, g_h);
    cudaGetSymbolAddress((void**)&gat,  g_gat);
    cudaGetSymbolAddress((void**)&ssrc, g_ssrc);
    cudaGetSymbolAddress((void**)&sdst, g_sdst);
    cudaGetSymbolAddress((void**)&x3,   g_x3);
    cudaGetSymbolAddress((void**)&gat3, g_gat3);

    // ---- CSR build (same every call; must be redone: no caching) ----
    k_zero_cnt<<<(NN + 255) / 256, 256>>>();
    k_count<<<(EE + 255) / 256, 256>>>(ei);
    k_scan<<<1, 1024>>>();
    k_fill_self<<<(NN + 255) / 256, 256>>>();
    k_fill<<<(EE + 255) / 256, 256>>>(ei);

    dim3 gemmGrid(4, (NN + 127) / 128);      // Nn=512
    dim3 gemmGrid3(1, (NN + 127) / 128);     // Nn=64
    const int T4 = NN * HC / 4;
    const int T4c = NN * CC / 4;

    // ---- encoder: bufA = x @ enc_W + enc_b ----
    k_gemm<<<gemmGrid, 256>>>(x, enc_W, enc_b, bufA, NN, 512, 512);

    // ---- layer 1 ----
    k_gemm<<<gemmGrid, 256>>>(bufA, W1, nullptr, hbuf, NN, 512, 512);
    k_scores<<<NN, 32 * HH>>>(hbuf, as1, ad1, ssrc, sdst, HH);
    k_agg8<<<NN, 128>>>(hbuf, ssrc, sdst, b1, gat);
    k_bnzero<<<1, HC>>>(HC);
    k_bnstats<<<100, HC>>>(gat, HC, 100);
    k_bnfinal<<<1, HC>>>(g1, be1, HC);
    k_bnapply<<<512, 256>>>(gat, bufA, bufB, HC, 1, T4);

    // ---- layer 2 ----
    k_gemm<<<gemmGrid, 256>>>(bufB, W2, nullptr, hbuf, NN, 512, 512);
    k_scores<<<NN, 32 * HH>>>(hbuf, as2, ad2, ssrc, sdst, HH);
    k_agg8<<<NN, 128>>>(hbuf, ssrc, sdst, b2, gat);
    k_bnzero<<<1, HC>>>(HC);
    k_bnstats<<<100, HC>>>(gat, HC, 100);
    k_bnfinal<<<1, HC>>>(g2, be2, HC);
    k_bnapply<<<512, 256>>>(gat, bufB, bufA, HC, 1, T4);

    // ---- layer 3 (H=1, C=64) ----
    k_gemm<<<gemmGrid3, 256>>>(bufA, W3, nullptr, x3, NN, 512, 64);
    k_scores<<<NN, 32>>>(x3, as3, ad3, ssrc, sdst, 1);
    k_agg1<<<NN, 64>>>(x3, ssrc, sdst, b3, gat3);
    k_bnzero<<<1, CC>>>(CC);
    k_bnstats<<<100, CC>>>(gat3, CC, 100);
    k_bnfinal<<<1, CC>>>(g3, be3, CC);
    k_bnapply<<<256, 256>>>(gat3, nullptr, x3, CC, 0, T4c);

    // ---- pool + classifier ----
    k_poolzero<<<(GG * CC + 255) / 256, 256>>>();
    k_pool<<<NN, CC>>>(x3, batch);
    k_final<<<GG, NCLS>>>(linW, linb, out);
}

// round 5
// speedup vs baseline: 1.8509x; 1.8509x over previous
#include <cuda_runtime.h>
#include <cuda_bf16.h>
#include <math.h>
#include <stdint.h>

// Problem constants
#define NN    10000          // nodes
#define EE    160000         // edges (without self loops)
#define EP    170000         // edges + self loops
#define HH    8              // heads (layers 1,2)
#define CC    64             // channels per head
#define HC    512            // H*C
#define GG    64             // graphs
#define NCLS  64             // classes

// ---------------- device scratch (static; no allocation) ----------------
__device__ float g_bufA[NN * HC];
__device__ float g_bufB[NN * HC];
__device__ float g_h[NN * HC];
__device__ float g_gat[NN * HC];
__device__ float g_ssrc[NN * HH];
__device__ float g_sdst[NN * HH];
__device__ float g_x3[NN * CC];
__device__ float g_gat3[NN * CC];
__device__ int   g_rowptr[NN + 1];
__device__ int   g_cnt[NN];
__device__ int   g_csrc[EP];
__device__ float g_bnsum[HC];
__device__ float g_bnsq[HC];
__device__ float g_scale[HC];
__device__ float g_shift[HC];
__device__ float g_pool[GG * CC];
__device__ float g_cntg[GG];
// bf16 split buffers for tensor-core GEMM
__device__ __nv_bfloat16 g_Ah[NN * HC];
__device__ __nv_bfloat16 g_Al[NN * HC];
__device__ __nv_bfloat16 g_Wth[HC * HC];   // transposed weight hi [N,K]
__device__ __nv_bfloat16 g_Wtl[HC * HC];   // transposed weight lo [N,K]

// ======================= warp-MMA helpers (family-safe PTX) =======================
__device__ __forceinline__ uint32_t smem_to_u32(const void* p) {
    uint32_t a;
    asm("{ .reg .u64 t; cvta.to.shared.u64 t, %1; cvt.u32.u64 %0, t; }" : "=r"(a) : "l"(p));
    return a;
}

__device__ __forceinline__ void ldm_x4(uint32_t* r, uint32_t addr) {
    asm volatile("ldmatrix.sync.aligned.m8n8.x4.shared.b16 {%0,%1,%2,%3}, [%4];"
                 : "=r"(r[0]), "=r"(r[1]), "=r"(r[2]), "=r"(r[3]) : "r"(addr));
}

__device__ __forceinline__ void mma16816(float* c, const uint32_t* a, const uint32_t* b) {
    asm volatile(
        "mma.sync.aligned.m16n8k16.row.col.f32.bf16.bf16.f32 "
        "{%0,%1,%2,%3}, {%4,%5,%6,%7}, {%8,%9}, {%0,%1,%2,%3};"
        : "+f"(c[0]), "+f"(c[1]), "+f"(c[2]), "+f"(c[3])
        : "r"(a[0]), "r"(a[1]), "r"(a[2]), "r"(a[3]), "r"(b[0]), "r"(b[1]));
}

// ======================= bf16 split conversions =======================
__global__ void k_cvt_act(const float* __restrict__ in, __nv_bfloat16* __restrict__ hi,
                          __nv_bfloat16* __restrict__ lo, int n4) {
    int i = blockIdx.x * blockDim.x + threadIdx.x;
    int stride = gridDim.x * blockDim.x;
    for (; i < n4; i += stride) {
        float4 v = ((const float4*)in)[i];
        __nv_bfloat16 h0 = __float2bfloat16(v.x);
        __nv_bfloat16 h1 = __float2bfloat16(v.y);
        __nv_bfloat16 h2 = __float2bfloat16(v.z);
        __nv_bfloat16 h3 = __float2bfloat16(v.w);
        __nv_bfloat16 l0 = __float2bfloat16(v.x - __bfloat162float(h0));
        __nv_bfloat16 l1 = __float2bfloat16(v.y - __bfloat162float(h1));
        __nv_bfloat16 l2 = __float2bfloat16(v.z - __bfloat162float(h2));
        __nv_bfloat16 l3 = __float2bfloat16(v.w - __bfloat162float(h3));
        ((__nv_bfloat162*)hi)[2 * i]     = __halves2bfloat162(h0, h1);
        ((__nv_bfloat162*)hi)[2 * i + 1] = __halves2bfloat162(h2, h3);
        ((__nv_bfloat162*)lo)[2 * i]     = __halves2bfloat162(l0, l1);
        ((__nv_bfloat162*)lo)[2 * i + 1] = __halves2bfloat162(l2, l3);
    }
}

// transpose W[K,Nn] -> Wt[Nn,K] as bf16 hi/lo; block (32,8), grid (Nn/32, K/32)
__global__ void k_cvt_wT(const float* __restrict__ W, __nv_bfloat16* __restrict__ th,
                         __nv_bfloat16* __restrict__ tl, int K, int Nn) {
    __shared__ float t[32][33];
    int bx = blockIdx.x * 32;  // n
    int by = blockIdx.y * 32;  // k
    int tx = threadIdx.x, ty = threadIdx.y;
#pragma unroll
    for (int j = 0; j < 32; j += 8)
        t[ty + j][tx] = W[(size_t)(by + ty + j) * Nn + bx + tx];
    __syncthreads();
#pragma unroll
    for (int j = 0; j < 32; j += 8) {
        float v = t[tx][ty + j];
        __nv_bfloat16 h = __float2bfloat16(v);
        __nv_bfloat16 l = __float2bfloat16(v - __bfloat162float(h));
        size_t o = (size_t)(bx + ty + j) * K + by + tx;
        th[o] = h; tl[o] = l;
    }
}

// ======================= warp-MMA GEMM =======================
// C[M,Nn] = A[M,512] @ Wt^T, Wt[Nn,512]; 2-term bf16 split (Ah*Bh + Al*Bh + Ah*Bl), fp32 acc.
// BM=128, BN=64, BK=64, K=512 fixed. 256 threads = 8 warps (4 over M x 2 over N), warp tile 32x32.
#define AH_OFF 0
#define AL_OFF 16384
#define BH_OFF 32768
#define BL_OFF 40960
#define SMEM_GEMM 49152

__global__ __launch_bounds__(256, 2)
void k_gemm_mma(const __nv_bfloat16* __restrict__ Ah, const __nv_bfloat16* __restrict__ Al,
                const __nv_bfloat16* __restrict__ Bh, const __nv_bfloat16* __restrict__ Bl,
                const float* __restrict__ bias, float* __restrict__ Cm, int M, int Nn) {
    extern __shared__ char smem[];
    const uint32_t sb = smem_to_u32(smem);
    const int tid = threadIdx.x;
    const int lane = tid & 31;
    const int wid = tid >> 5;
    const int warpM = wid & 3;     // 0..3
    const int warpN = wid >> 2;    // 0..1
    const int bm = blockIdx.y * 128;
    const int bn = blockIdx.x * 64;

    float acc[2][4][4];
#pragma unroll
    for (int mt = 0; mt < 2; mt++)
#pragma unroll
        for (int nt = 0; nt < 4; nt++)
#pragma unroll
            for (int r = 0; r < 4; r++) acc[mt][nt][r] = 0.f;

    // precomputed ldmatrix lane address components
    const uint32_t aRow = (uint32_t)(warpM * 32 + (lane & 15));
    const uint32_t aC16b = (uint32_t)(lane >> 4);
    const uint32_t bRow = (uint32_t)(warpN * 32 + ((lane >> 4) << 3) + (lane & 7));
    const uint32_t bC16b = (uint32_t)((lane >> 3) & 1);

    for (int kb = 0; kb < 8; kb++) {
        // ---- global -> smem (SW128 swizzled, 128B rows of 64 bf16) ----
        // A hi/lo: 128 rows x 8 chunks of 16B
#pragma unroll
        for (int it = 0; it < 4; it++) {
            int idx = tid + it * 256;
            int r = idx >> 3, c16 = idx & 7;
            uint32_t so = (uint32_t)(r * 128 + c16 * 16);
            so ^= (so >> 3) & 0x70;
            int gr = bm + r;
            uint4 vh = make_uint4(0, 0, 0, 0), vl = make_uint4(0, 0, 0, 0);
            if (gr < M) {
                size_t goff = (size_t)gr * 512 + kb * 64 + c16 * 8;
                vh = *(const uint4*)(Ah + goff);
                vl = *(const uint4*)(Al + goff);
            }
            *(uint4*)(smem + AH_OFF + so) = vh;
            *(uint4*)(smem + AL_OFF + so) = vl;
        }
        // B hi/lo: 64 rows x 8 chunks
#pragma unroll
        for (int it = 0; it < 2; it++) {
            int idx = tid + it * 256;
            int r = idx >> 3, c16 = idx & 7;
            uint32_t so = (uint32_t)(r * 128 + c16 * 16);
            so ^= (so >> 3) & 0x70;
            size_t goff = (size_t)(bn + r) * 512 + kb * 64 + c16 * 8;
            *(uint4*)(smem + BH_OFF + so) = *(const uint4*)(Bh + goff);
            *(uint4*)(smem + BL_OFF + so) = *(const uint4*)(Bl + goff);
        }
        __syncthreads();

        // ---- 4 k-steps of 16 ----
#pragma unroll
        for (int ks = 0; ks < 4; ks++) {
            uint32_t ah[2][4], al[2][4], bh[2][4], bl[2][4];
            uint32_t ac16 = (uint32_t)(ks * 2) + aC16b;
#pragma unroll
            for (int mt = 0; mt < 2; mt++) {
                uint32_t off = (aRow + mt * 16) * 128 + ac16 * 16;
                off ^= (off >> 3) & 0x70;
                ldm_x4(ah[mt], sb + AH_OFF + off);
                ldm_x4(al[mt], sb + AL_OFF + off);
            }
            uint32_t bc16 = (uint32_t)(ks * 2) + bC16b;
#pragma unroll
            for (int half = 0; half < 2; half++) {
                uint32_t off = (bRow + half * 16) * 128 + bc16 * 16;
                off ^= (off >> 3) & 0x70;
                ldm_x4(bh[half], sb + BH_OFF + off);
                ldm_x4(bl[half], sb + BL_OFF + off);
            }
#pragma unroll
            for (int mt = 0; mt < 2; mt++) {
#pragma unroll
                for (int nt = 0; nt < 4; nt++) {
                    const uint32_t* bhf = &bh[nt >> 1][(nt & 1) * 2];
                    const uint32_t* blf = &bl[nt >> 1][(nt & 1) * 2];
                    mma16816(acc[mt][nt], ah[mt], bhf);
                    mma16816(acc[mt][nt], al[mt], bhf);
                    mma16816(acc[mt][nt], ah[mt], blf);
                }
            }
        }
        __syncthreads();
    }

    // ---- epilogue ----
    const int rowBase = bm + warpM * 32 + (lane >> 2);
    const int colBase = bn + warpN * 32 + (lane & 3) * 2;
#pragma unroll
    for (int mt = 0; mt < 2; mt++) {
#pragma unroll
        for (int nt = 0; nt < 4; nt++) {
            int gc = colBase + nt * 8;
            float b0 = 0.f, b1 = 0.f;
            if (bias) { b0 = bias[gc]; b1 = bias[gc + 1]; }
            int r0 = rowBase + mt * 16;
            if (r0 < M) {
                float2 o = make_float2(acc[mt][nt][0] + b0, acc[mt][nt][1] + b1);
                *(float2*)(Cm + (size_t)r0 * Nn + gc) = o;
            }
            int r1 = r0 + 8;
            if (r1 < M) {
                float2 o = make_float2(acc[mt][nt][2] + b0, acc[mt][nt][3] + b1);
                *(float2*)(Cm + (size_t)r1 * Nn + gc) = o;
            }
        }
    }
}

// ---------------- CSR build ----------------
__global__ void k_zero_cnt() {
    int i = blockIdx.x * blockDim.x + threadIdx.x;
    if (i < NN) g_cnt[i] = 0;
}

__global__ void k_count(const int* __restrict__ ei) {
    int e = blockIdx.x * blockDim.x + threadIdx.x;
    if (e < EE) atomicAdd(&g_cnt[ei[EE + e]], 1);
}

__global__ void k_scan() {
    __shared__ int sh[1024];
    __shared__ int carry;
    int tid = threadIdx.x;
    if (tid == 0) carry = 0;
    __syncthreads();
    for (int base = 0; base < NN; base += 1024) {
        int i = base + tid;
        int v = (i < NN) ? (g_cnt[i] + 1) : 0;   // +1 self loop
        sh[tid] = v;
        __syncthreads();
        for (int off = 1; off < 1024; off <<= 1) {
            int t = (tid >= off) ? sh[tid - off] : 0;
            __syncthreads();
            sh[tid] += t;
            __syncthreads();
        }
        if (i < NN) g_rowptr[i + 1] = carry + sh[tid];
        __syncthreads();
        if (tid == 1023) carry += sh[1023];
        __syncthreads();
    }
    if (tid == 0) g_rowptr[0] = 0;
}

__global__ void k_fill_self() {
    int i = blockIdx.x * blockDim.x + threadIdx.x;
    if (i < NN) {
        int rp = g_rowptr[i];
        g_csrc[rp] = i;          // self loop first
        g_cnt[i] = rp + 1;       // cursor
    }
}

__global__ void k_fill(const int* __restrict__ ei) {
    int e = blockIdx.x * blockDim.x + threadIdx.x;
    if (e < EE) {
        int dst = ei[EE + e];
        int slot = atomicAdd(&g_cnt[dst], 1);
        g_csrc[slot] = ei[e];
    }
}

// ---------------- attention score precompute ----------------
__global__ void k_scores(const float* __restrict__ h, const float* __restrict__ a_s,
                         const float* __restrict__ a_d, float* __restrict__ ssrc,
                         float* __restrict__ sdst, int Hh) {
    int n = blockIdx.x;
    int warp = threadIdx.x >> 5, lane = threadIdx.x & 31;
    const float* hp = h + (size_t)n * Hh * CC + warp * CC;
    float v0 = hp[lane], v1 = hp[lane + 32];
    float s1 = v0 * a_s[warp * CC + lane] + v1 * a_s[warp * CC + lane + 32];
    float s2 = v0 * a_d[warp * CC + lane] + v1 * a_d[warp * CC + lane + 32];
#pragma unroll
    for (int o = 16; o >= 1; o >>= 1) {
        s1 += __shfl_xor_sync(0xffffffffu, s1, o);
        s2 += __shfl_xor_sync(0xffffffffu, s2, o);
    }
    if (lane == 0) { ssrc[n * Hh + warp] = s1; sdst[n * Hh + warp] = s2; }
}

__device__ __forceinline__ float lrelu02(float x) { return x > 0.f ? x : 0.2f * x; }

// ---------------- GAT aggregation, H=8 ----------------
__global__ void k_agg8(const float* __restrict__ hbuf, const float* __restrict__ ssrc,
                       const float* __restrict__ sdst, const float* __restrict__ bias,
                       float* __restrict__ out) {
    int dstn = blockIdx.x;
    int tid = threadIdx.x;
    __shared__ float sh_sdst[HH], sh_m[HH], sh_s[HH];
    if (tid < HH) sh_sdst[tid] = sdst[dstn * HH + tid];
    __syncthreads();
    int beg = g_rowptr[dstn], end = g_rowptr[dstn + 1];
    int warp = tid >> 5, lane = tid & 31;
    {
        int hh = warp * 2 + (lane >> 4);
        int sub = lane & 15;
        float sd = sh_sdst[hh];
        float mx = -3.4e38f;
        for (int i = beg + sub; i < end; i += 16)
            mx = fmaxf(mx, lrelu02(ssrc[g_csrc[i] * HH + hh] + sd));
#pragma unroll
        for (int o = 1; o < 16; o <<= 1) mx = fmaxf(mx, __shfl_xor_sync(0xffffffffu, mx, o));
        float se = 0.f;
        for (int i = beg + sub; i < end; i += 16)
            se += __expf(lrelu02(ssrc[g_csrc[i] * HH + hh] + sd) - mx);
#pragma unroll
        for (int o = 1; o < 16; o <<= 1) se += __shfl_xor_sync(0xffffffffu, se, o);
        if (sub == 0) { sh_m[hh] = mx; sh_s[hh] = se; }
    }
    __syncthreads();
    int hh = tid >> 4;
    int c4 = (tid & 15) << 2;
    float m = sh_m[hh];
    float sinv = 1.f / (sh_s[hh] + 1e-16f);
    float sd = sh_sdst[hh];
    float4 acc = make_float4(0.f, 0.f, 0.f, 0.f);
    for (int i = beg; i < end; i++) {
        int s = g_csrc[i];
        float alpha = __expf(lrelu02(ssrc[s * HH + hh] + sd) - m) * sinv;
        float4 v = *(const float4*)(hbuf + (size_t)s * HC + hh * CC + c4);
        acc.x = fmaf(alpha, v.x, acc.x);
        acc.y = fmaf(alpha, v.y, acc.y);
        acc.z = fmaf(alpha, v.z, acc.z);
        acc.w = fmaf(alpha, v.w, acc.w);
    }
    float4 bb = *(const float4*)(bias + hh * CC + c4);
    acc.x += bb.x; acc.y += bb.y; acc.z += bb.z; acc.w += bb.w;
    *(float4*)(out + (size_t)dstn * HC + hh * CC + c4) = acc;
}

// ---------------- GAT aggregation, H=1 C=64 ----------------
__global__ void k_agg1(const float* __restrict__ h3, const float* __restrict__ ssrc,
                       const float* __restrict__ sdst, const float* __restrict__ bias,
                       float* __restrict__ out) {
    int dstn = blockIdx.x;
    int tid = threadIdx.x;
    __shared__ float sh_m, sh_s;
    float sd = sdst[dstn];
    int beg = g_rowptr[dstn], end = g_rowptr[dstn + 1];
    if (tid < 32) {
        float mx = -3.4e38f;
        for (int i = beg + tid; i < end; i += 32)
            mx = fmaxf(mx, lrelu02(ssrc[g_csrc[i]] + sd));
#pragma unroll
        for (int o = 1; o < 32; o <<= 1) mx = fmaxf(mx, __shfl_xor_sync(0xffffffffu, mx, o));
        float se = 0.f;
        for (int i = beg + tid; i < end; i += 32)
            se += __expf(lrelu02(ssrc[g_csrc[i]] + sd) - mx);
#pragma unroll
        for (int o = 1; o < 32; o <<= 1) se += __shfl_xor_sync(0xffffffffu, se, o);
        if (tid == 0) { sh_m = mx; sh_s = se; }
    }
    __syncthreads();
    float m = sh_m;
    float sinv = 1.f / (sh_s + 1e-16f);
    float acc = 0.f;
    for (int i = beg; i < end; i++) {
        int s = g_csrc[i];
        float alpha = __expf(lrelu02(ssrc[s] + sd) - m) * sinv;
        acc = fmaf(alpha, h3[(size_t)s * CC + tid], acc);
    }
    out[(size_t)dstn * CC + tid] = acc + bias[tid];
}

// ---------------- BatchNorm (training stats) ----------------
__global__ void k_bnzero(int Cdim) {
    int c = threadIdx.x;
    if (c < Cdim) { g_bnsum[c] = 0.f; g_bnsq[c] = 0.f; }
}

__global__ void k_bnstats(const float* __restrict__ x, int Cdim, int rowsPerBlock) {
    int c = threadIdx.x;
    int r0 = blockIdx.x * rowsPerBlock;
    int r1 = min(r0 + rowsPerBlock, NN);
    float s = 0.f, q = 0.f;
    for (int r = r0; r < r1; r++) {
        float v = x[(size_t)r * Cdim + c];
        s += v; q = fmaf(v, v, q);
    }
    atomicAdd(&g_bnsum[c], s);
    atomicAdd(&g_bnsq[c], q);
}

__global__ void k_bnfinal(const float* __restrict__ g, const float* __restrict__ be, int Cdim) {
    int c = threadIdx.x;
    if (c >= Cdim) return;
    float mu = g_bnsum[c] / (float)NN;
    float var = g_bnsq[c] / (float)NN - mu * mu;
    var = fmaxf(var, 0.f);
    float inv = rsqrtf(var + 1e-5f);
    float sc = g[c] * inv;
    g_scale[c] = sc;
    g_shift[c] = be[c] - sc * mu;
}

__global__ void k_bnapply(const float* __restrict__ in, const float* __restrict__ res,
                          float* __restrict__ out, int Cdim, int doElu, int total4) {
    int i = blockIdx.x * blockDim.x + threadIdx.x;
    int stride = gridDim.x * blockDim.x;
    int c4cnt = Cdim >> 2;
    for (; i < total4; i += stride) {
        int c4 = (i % c4cnt) << 2;
        float4 v = ((const float4*)in)[i];
        float4 sc = *(const float4*)&g_scale[c4];
        float4 sh = *(const float4*)&g_shift[c4];
        float o0 = fmaf(sc.x, v.x, sh.x);
        float o1 = fmaf(sc.y, v.y, sh.y);
        float o2 = fmaf(sc.z, v.z, sh.z);
        float o3 = fmaf(sc.w, v.w, sh.w);
        if (doElu) {
            o0 = o0 > 0.f ? o0 : expm1f(o0);
            o1 = o1 > 0.f ? o1 : expm1f(o1);
            o2 = o2 > 0.f ? o2 : expm1f(o2);
            o3 = o3 > 0.f ? o3 : expm1f(o3);
        }
        if (res) {
            float4 rv = ((const float4*)res)[i];
            o0 += rv.x; o1 += rv.y; o2 += rv.z; o3 += rv.w;
        }
        float4 o; o.x = o0; o.y = o1; o.z = o2; o.w = o3;
        ((float4*)out)[i] = o;
    }
}

// ---------------- pooling + classifier ----------------
__global__ void k_poolzero() {
    int i = threadIdx.x + blockIdx.x * blockDim.x;
    if (i < GG * CC) g_pool[i] = 0.f;
    if (i < GG) g_cntg[i] = 0.f;
}

__global__ void k_pool(const float* __restrict__ x3, const int* __restrict__ batch) {
    int n = blockIdx.x;
    int c = threadIdx.x;
    int g = batch[n];
    atomicAdd(&g_pool[g * CC + c], x3[(size_t)n * CC + c]);
    if (c == 0) atomicAdd(&g_cntg[g], 1.0f);
}

__global__ void k_final(const float* __restrict__ linW, const float* __restrict__ linb,
                        float* __restrict__ out) {
    int g = blockIdx.x;
    int j = threadIdx.x;
    __shared__ float xg[CC];
    float cv = fmaxf(g_cntg[g], 1.0f);
    xg[j] = g_pool[g * CC + j] / cv;
    __syncthreads();
    float acc = linb[j];
#pragma unroll
    for (int c = 0; c < CC; c++) acc = fmaf(xg[c], linW[c * NCLS + j], acc);
    out[g * NCLS + j] = acc;
}

// ---------------- host side ----------------
extern "C" void kernel_launch(void* const* d_in, const int* in_sizes, int n_in,
                              void* d_out, int out_size) {
    const float* x      = (const float*)d_in[0];
    const int*   ei     = (const int*)d_in[1];
    const int*   batch  = (const int*)d_in[2];
    const float* enc_W  = (const float*)d_in[3];
    const float* enc_b  = (const float*)d_in[4];
    const float* W1     = (const float*)d_in[5];
    const float* as1    = (const float*)d_in[6];
    const float* ad1    = (const float*)d_in[7];
    const float* b1     = (const float*)d_in[8];
    const float* g1     = (const float*)d_in[9];
    const float* be1    = (const float*)d_in[10];
    const float* W2     = (const float*)d_in[11];
    const float* as2    = (const float*)d_in[12];
    const float* ad2    = (const float*)d_in[13];
    const float* b2     = (const float*)d_in[14];
    const float* g2     = (const float*)d_in[15];
    const float* be2    = (const float*)d_in[16];
    const float* W3     = (const float*)d_in[17];
    const float* as3    = (const float*)d_in[18];
    const float* ad3    = (const float*)d_in[19];
    const float* b3     = (const float*)d_in[20];
    const float* g3     = (const float*)d_in[21];
    const float* be3    = (const float*)d_in[22];
    const float* linW   = (const float*)d_in[23];
    const float* linb   = (const float*)d_in[24];
    float* out = (float*)d_out;

    float *bufA, *bufB, *hbuf, *gat, *ssrc, *sdst, *x3, *gat3;
    __nv_bfloat16 *Ah, *Al, *Wth, *Wtl;
    cudaGetSymbolAddress((void**)&bufA, g_bufA);
    cudaGetSymbolAddress((void**)&bufB, g_bufB);
    cudaGetSymbolAddress((void**)&hbuf, g_h);
    cudaGetSymbolAddress((void**)&gat,  g_gat);
    cudaGetSymbolAddress((void**)&ssrc, g_ssrc);
    cudaGetSymbolAddress((void**)&sdst, g_sdst);
    cudaGetSymbolAddress((void**)&x3,   g_x3);
    cudaGetSymbolAddress((void**)&gat3, g_gat3);
    cudaGetSymbolAddress((void**)&Ah,   g_Ah);
    cudaGetSymbolAddress((void**)&Al,   g_Al);
    cudaGetSymbolAddress((void**)&Wth,  g_Wth);
    cudaGetSymbolAddress((void**)&Wtl,  g_Wtl);

    cudaFuncSetAttribute(k_gemm_mma, cudaFuncAttributeMaxDynamicSharedMemorySize, SMEM_GEMM);

    // ---- CSR build ----
    k_zero_cnt<<<(NN + 255) / 256, 256>>>();
    k_count<<<(EE + 255) / 256, 256>>>(ei);
    k_scan<<<1, 1024>>>();
    k_fill_self<<<(NN + 255) / 256, 256>>>();
    k_fill<<<(EE + 255) / 256, 256>>>(ei);

    dim3 gGrid(HC / 64, (NN + 127) / 128);   // Nn=512 -> 8 x 79
    dim3 gGrid3(1, (NN + 127) / 128);        // Nn=64  -> 1 x 79
    dim3 wtGrid(HC / 32, HC / 32), wtBlk(32, 8);
    dim3 wtGrid3(CC / 32, HC / 32);
    const int A4 = NN * HC / 4;
    const int T4 = NN * HC / 4;
    const int T4c = NN * CC / 4;

    // ---- encoder: bufA = x @ enc_W + enc_b ----
    k_cvt_act<<<512, 256>>>(x, Ah, Al, A4);
    k_cvt_wT<<<wtGrid, wtBlk>>>(enc_W, Wth, Wtl, HC, HC);
    k_gemm_mma<<<gGrid, 256, SMEM_GEMM>>>(Ah, Al, Wth, Wtl, enc_b, bufA, NN, HC);

    // ---- layer 1 ----
    k_cvt_act<<<512, 256>>>(bufA, Ah, Al, A4);
    k_cvt_wT<<<wtGrid, wtBlk>>>(W1, Wth, Wtl, HC, HC);
    k_gemm_mma<<<gGrid, 256, SMEM_GEMM>>>(Ah, Al, Wth, Wtl, nullptr, hbuf, NN, HC);
    k_scores<<<NN, 32 * HH>>>(hbuf, as1, ad1, ssrc, sdst, HH);
    k_agg8<<<NN, 128>>>(hbuf, ssrc, sdst, b1, gat);
    k_bnzero<<<1, HC>>>(HC);
    k_bnstats<<<100, HC>>>(gat, HC, 100);
    k_bnfinal<<<1, HC>>>(g1, be1, HC);
    k_bnapply<<<512, 256>>>(gat, bufA, bufB, HC, 1, T4);

    // ---- layer 2 ----
    k_cvt_act<<<512, 256>>>(bufB, Ah, Al, A4);
    k_cvt_wT<<<wtGrid, wtBlk>>>(W2, Wth, Wtl, HC, HC);
    k_gemm_mma<<<gGrid, 256, SMEM_GEMM>>>(Ah, Al, Wth, Wtl, nullptr, hbuf, NN, HC);
    k_scores<<<NN, 32 * HH>>>(hbuf, as2, ad2, ssrc, sdst, HH);
    k_agg8<<<NN, 128>>>(hbuf, ssrc, sdst, b2, gat);
    k_bnzero<<<1, HC>>>(HC);
    k_bnstats<<<100, HC>>>(gat, HC, 100);
    k_bnfinal<<<1, HC>>>(g2, be2, HC);
    k_bnapply<<<512, 256>>>(gat, bufB, bufA, HC, 1, T4);

    // ---- layer 3 (H=1, C=64) ----
    k_cvt_act<<<512, 256>>>(bufA, Ah, Al, A4);
    k_cvt_wT<<<wtGrid3, wtBlk>>>(W3, Wth, Wtl, HC, CC);
    k_gemm_mma<<<gGrid3, 256, SMEM_GEMM>>>(Ah, Al, Wth, Wtl, nullptr, x3, NN, CC);
    k_scores<<<NN, 32>>>(x3, as3, ad3, ssrc, sdst, 1);
    k_agg1<<<NN, 64>>>(x3, ssrc, sdst, b3, gat3);
    k_bnzero<<<1, CC>>>(CC);
    k_bnstats<<<100, CC>>>(gat3, CC, 100);
    k_bnfinal<<<1, CC>>>(g3, be3, CC);
    k_bnapply<<<256, 256>>>(gat3, nullptr, x3, CC, 0, T4c);

    // ---- pool + classifier ----
    k_poolzero<<<(GG * CC + 255) / 256, 256>>>();
    k_pool<<<NN, CC>>>(x3, batch);
    k_final<<<GG, NCLS>>>(linW, linb, out);
}

// round 7
// speedup vs baseline: 2.0566x; 1.1112x over previous
#include <cuda_runtime.h>
#include <cuda_bf16.h>
#include <math.h>
#include <stdint.h>

// Problem constants
#define NN    10000
#define EE    160000
#define EP    170000
#define HH    8
#define CC    64
#define HC    512
#define GG    64
#define NCLS  64
#define NBN   100            // bn partial blocks

// ---------------- device scratch ----------------
__device__ float g_bufA[NN * HC];
__device__ float g_bufB[NN * HC];
__device__ float g_h[NN * HC];
__device__ float g_gat[NN * HC];
__device__ float g_ssrc[NN * HH];
__device__ float g_sdst[NN * HH];
__device__ float g_x3[NN * CC];
__device__ float g_gat3[NN * CC];
__device__ int   g_rowptr[NN + 1];
__device__ int   g_cnt[NN];
__device__ int   g_csrc[EP];
__device__ float g_bnpart[NBN * HC];
__device__ float g_bnpart2[NBN * HC];
__device__ float g_scale[HC];
__device__ float g_shift[HC];
__device__ float g_pool[GG * CC];
__device__ float g_cntg[GG];
__device__ __nv_bfloat16 g_Ah[NN * HC];
__device__ __nv_bfloat16 g_Al[NN * HC];
__device__ __nv_bfloat16 g_Ah2[NN * HC];
__device__ __nv_bfloat16 g_Al2[NN * HC];
__device__ __nv_bfloat16 g_Wth[HC * HC];
__device__ __nv_bfloat16 g_Wtl[HC * HC];

// ======================= helpers =======================
__device__ __forceinline__ uint32_t smem_to_u32(const void* p) {
    uint32_t a;
    asm("{ .reg .u64 t; cvta.to.shared.u64 t, %1; cvt.u32.u64 %0, t; }" : "=r"(a) : "l"(p));
    return a;
}
__device__ __forceinline__ void ldm_x4(uint32_t* r, uint32_t addr) {
    asm volatile("ldmatrix.sync.aligned.m8n8.x4.shared.b16 {%0,%1,%2,%3}, [%4];"
                 : "=r"(r[0]), "=r"(r[1]), "=r"(r[2]), "=r"(r[3]) : "r"(addr));
}
__device__ __forceinline__ void mma16816(float* c, const uint32_t* a, const uint32_t* b) {
    asm volatile(
        "mma.sync.aligned.m16n8k16.row.col.f32.bf16.bf16.f32 "
        "{%0,%1,%2,%3}, {%4,%5,%6,%7}, {%8,%9}, {%0,%1,%2,%3};"
        : "+f"(c[0]), "+f"(c[1]), "+f"(c[2]), "+f"(c[3])
        : "r"(a[0]), "r"(a[1]), "r"(a[2]), "r"(a[3]), "r"(b[0]), "r"(b[1]));
}
__device__ __forceinline__ void cp16(uint32_t dst, const void* src, int sz) {
    asm volatile("cp.async.cg.shared.global [%0], [%1], 16, %2;"
                 :: "r"(dst), "l"(src), "r"(sz));
}
#define CP_COMMIT() asm volatile("cp.async.commit_group;" ::: "memory")
#define CP_WAIT(n)  asm volatile("cp.async.wait_group %0;" :: "n"(n) : "memory")

__device__ __forceinline__ void split_bf16(float v, __nv_bfloat16& h, __nv_bfloat16& l) {
    h = __float2bfloat16(v);
    l = __float2bfloat16(v - __bfloat162float(h));
}

// ======================= conversions =======================
__global__ void k_cvt_act(const float* __restrict__ in, __nv_bfloat16* __restrict__ hi,
                          __nv_bfloat16* __restrict__ lo, int n4) {
    int i = blockIdx.x * blockDim.x + threadIdx.x;
    int stride = gridDim.x * blockDim.x;
    for (; i < n4; i += stride) {
        float4 v = ((const float4*)in)[i];
        __nv_bfloat16 h0, h1, h2, h3, l0, l1, l2, l3;
        split_bf16(v.x, h0, l0); split_bf16(v.y, h1, l1);
        split_bf16(v.z, h2, l2); split_bf16(v.w, h3, l3);
        ((__nv_bfloat162*)hi)[2 * i]     = __halves2bfloat162(h0, h1);
        ((__nv_bfloat162*)hi)[2 * i + 1] = __halves2bfloat162(h2, h3);
        ((__nv_bfloat162*)lo)[2 * i]     = __halves2bfloat162(l0, l1);
        ((__nv_bfloat162*)lo)[2 * i + 1] = __halves2bfloat162(l2, l3);
    }
}

__global__ void k_cvt_wT(const float* __restrict__ W, __nv_bfloat16* __restrict__ th,
                         __nv_bfloat16* __restrict__ tl, int K, int Nn) {
    __shared__ float t[32][33];
    int bx = blockIdx.x * 32;
    int by = blockIdx.y * 32;
    int tx = threadIdx.x, ty = threadIdx.y;
#pragma unroll
    for (int j = 0; j < 32; j += 8)
        t[ty + j][tx] = W[(size_t)(by + ty + j) * Nn + bx + tx];
    __syncthreads();
#pragma unroll
    for (int j = 0; j < 32; j += 8) {
        float v = t[tx][ty + j];
        __nv_bfloat16 h, l;
        split_bf16(v, h, l);
        size_t o = (size_t)(bx + ty + j) * K + by + tx;
        th[o] = h; tl[o] = l;
    }
}

// ======================= cp.async double-buffered warp-MMA GEMM =======================
// C[M,Nn] = A[M,512] @ Wt^T, Wt[Nn,512]; 2-term bf16 split, fp32 acc.
// BM=128, BN=64, BK=64; 256 threads = 8 warps (4 M x 2 N), warp tile 32x32.
#define AH_OFF 0
#define AL_OFF 16384
#define BH_OFF 32768
#define BL_OFF 40960
#define STG    49152
#define SMEM_GEMM (2 * STG)

__global__ __launch_bounds__(256)
void k_gemm_mma(const __nv_bfloat16* __restrict__ Ah, const __nv_bfloat16* __restrict__ Al,
                const __nv_bfloat16* __restrict__ Bh, const __nv_bfloat16* __restrict__ Bl,
                const float* __restrict__ bias, float* __restrict__ Cm,
                __nv_bfloat16* __restrict__ outH, __nv_bfloat16* __restrict__ outL,
                int M, int Nn) {
    extern __shared__ char smem[];
    const uint32_t sb = smem_to_u32(smem);
    const int tid = threadIdx.x;
    const int lane = tid & 31;
    const int wid = tid >> 5;
    const int warpM = wid & 3;
    const int warpN = wid >> 2;
    const int bm = blockIdx.y * 128;
    const int bn = blockIdx.x * 64;

    float acc[2][4][4];
#pragma unroll
    for (int mt = 0; mt < 2; mt++)
#pragma unroll
        for (int nt = 0; nt < 4; nt++)
#pragma unroll
            for (int r = 0; r < 4; r++) acc[mt][nt][r] = 0.f;

    // async load of one k-block into stage buf
    auto issue = [&](int kb, int buf) {
        const uint32_t sbase = sb + buf * STG;
#pragma unroll
        for (int it = 0; it < 4; it++) {
            int idx = tid + it * 256;
            int r = idx >> 3, c16 = idx & 7;
            uint32_t so = (uint32_t)(r * 128 + c16 * 16);
            so ^= (so >> 3) & 0x70;
            int gr = bm + r;
            int grc = gr < M ? gr : 0;
            int sz = gr < M ? 16 : 0;
            size_t goff = (size_t)grc * 512 + kb * 64 + c16 * 8;
            cp16(sbase + AH_OFF + so, Ah + goff, sz);
            cp16(sbase + AL_OFF + so, Al + goff, sz);
        }
#pragma unroll
        for (int it = 0; it < 2; it++) {
            int idx = tid + it * 256;
            int r = idx >> 3, c16 = idx & 7;
            uint32_t so = (uint32_t)(r * 128 + c16 * 16);
            so ^= (so >> 3) & 0x70;
            size_t goff = (size_t)(bn + r) * 512 + kb * 64 + c16 * 8;
            cp16(sbase + BH_OFF + so, Bh + goff, 16);
            cp16(sbase + BL_OFF + so, Bl + goff, 16);
        }
    };

    const uint32_t aRow = (uint32_t)(warpM * 32 + (lane & 15));
    const uint32_t aC16b = (uint32_t)(lane >> 4);
    const uint32_t bRow = (uint32_t)(warpN * 32 + ((lane >> 4) << 3) + (lane & 7));
    const uint32_t bC16b = (uint32_t)((lane >> 3) & 1);

    issue(0, 0);
    CP_COMMIT();

    for (int kb = 0; kb < 8; kb++) {
        if (kb + 1 < 8) { issue(kb + 1, (kb + 1) & 1); CP_COMMIT(); }
        if (kb + 1 < 8) { CP_WAIT(1); } else { CP_WAIT(0); }
        __syncthreads();
        const uint32_t sbase = sb + (kb & 1) * STG;
#pragma unroll
        for (int ks = 0; ks < 4; ks++) {
            uint32_t ah[2][4], al[2][4], bh[2][4], bl[2][4];
            uint32_t ac16 = (uint32_t)(ks * 2) + aC16b;
#pragma unroll
            for (int mt = 0; mt < 2; mt++) {
                uint32_t off = (aRow + mt * 16) * 128 + ac16 * 16;
                off ^= (off >> 3) & 0x70;
                ldm_x4(ah[mt], sbase + AH_OFF + off);
                ldm_x4(al[mt], sbase + AL_OFF + off);
            }
            uint32_t bc16 = (uint32_t)(ks * 2) + bC16b;
#pragma unroll
            for (int half = 0; half < 2; half++) {
                uint32_t off = (bRow + half * 16) * 128 + bc16 * 16;
                off ^= (off >> 3) & 0x70;
                ldm_x4(bh[half], sbase + BH_OFF + off);
                ldm_x4(bl[half], sbase + BL_OFF + off);
            }
#pragma unroll
            for (int mt = 0; mt < 2; mt++) {
#pragma unroll
                for (int nt = 0; nt < 4; nt++) {
                    const uint32_t* bhf = &bh[nt >> 1][(nt & 1) * 2];
                    const uint32_t* blf = &bl[nt >> 1][(nt & 1) * 2];
                    mma16816(acc[mt][nt], ah[mt], bhf);
                    mma16816(acc[mt][nt], al[mt], bhf);
                    mma16816(acc[mt][nt], ah[mt], blf);
                }
            }
        }
        __syncthreads();
    }

    // ---- epilogue (+ optional bf16 split output) ----
    const int rowBase = bm + warpM * 32 + (lane >> 2);
    const int colBase = bn + warpN * 32 + (lane & 3) * 2;
#pragma unroll
    for (int mt = 0; mt < 2; mt++) {
#pragma unroll
        for (int nt = 0; nt < 4; nt++) {
            int gc = colBase + nt * 8;
            float b0 = 0.f, b1 = 0.f;
            if (bias) { b0 = bias[gc]; b1 = bias[gc + 1]; }
#pragma unroll
            for (int half = 0; half < 2; half++) {
                int r = rowBase + mt * 16 + half * 8;
                if (r < M) {
                    float v0 = acc[mt][nt][half * 2] + b0;
                    float v1 = acc[mt][nt][half * 2 + 1] + b1;
                    *(float2*)(Cm + (size_t)r * Nn + gc) = make_float2(v0, v1);
                    if (outH) {
                        __nv_bfloat16 h0, h1, l0, l1;
                        split_bf16(v0, h0, l0);
                        split_bf16(v1, h1, l1);
                        *(__nv_bfloat162*)(outH + (size_t)r * Nn + gc) = __halves2bfloat162(h0, h1);
                        *(__nv_bfloat162*)(outL + (size_t)r * Nn + gc) = __halves2bfloat162(l0, l1);
                    }
                }
            }
        }
    }
}

// ---------------- CSR build ----------------
__global__ void k_zero_cnt() {
    int i = blockIdx.x * blockDim.x + threadIdx.x;
    if (i < NN) g_cnt[i] = 0;
}
__global__ void k_count(const int* __restrict__ ei) {
    int e = blockIdx.x * blockDim.x + threadIdx.x;
    if (e < EE) atomicAdd(&g_cnt[ei[EE + e]], 1);
}
__global__ void k_scan() {
    __shared__ int sh[1024];
    __shared__ int carry;
    int tid = threadIdx.x;
    if (tid == 0) carry = 0;
    __syncthreads();
    for (int base = 0; base < NN; base += 1024) {
        int i = base + tid;
        int v = (i < NN) ? (g_cnt[i] + 1) : 0;
        sh[tid] = v;
        __syncthreads();
        for (int off = 1; off < 1024; off <<= 1) {
            int t = (tid >= off) ? sh[tid - off] : 0;
            __syncthreads();
            sh[tid] += t;
            __syncthreads();
        }
        if (i < NN) g_rowptr[i + 1] = carry + sh[tid];
        __syncthreads();
        if (tid == 1023) carry += sh[1023];
        __syncthreads();
    }
    if (tid == 0) g_rowptr[0] = 0;
}
__global__ void k_fill_self() {
    int i = blockIdx.x * blockDim.x + threadIdx.x;
    if (i < NN) {
        int rp = g_rowptr[i];
        g_csrc[rp] = i;
        g_cnt[i] = rp + 1;
    }
}
__global__ void k_fill(const int* __restrict__ ei) {
    int e = blockIdx.x * blockDim.x + threadIdx.x;
    if (e < EE) {
        int dst = ei[EE + e];
        int slot = atomicAdd(&g_cnt[dst], 1);
        g_csrc[slot] = ei[e];
    }
}

// ---------------- attention score precompute ----------------
__global__ void k_scores(const float* __restrict__ h, const float* __restrict__ a_s,
                         const float* __restrict__ a_d, float* __restrict__ ssrc,
                         float* __restrict__ sdst, int Hh) {
    int n = blockIdx.x;
    int warp = threadIdx.x >> 5, lane = threadIdx.x & 31;
    const float* hp = h + (size_t)n * Hh * CC + warp * CC;
    float v0 = hp[lane], v1 = hp[lane + 32];
    float s1 = v0 * a_s[warp * CC + lane] + v1 * a_s[warp * CC + lane + 32];
    float s2 = v0 * a_d[warp * CC + lane] + v1 * a_d[warp * CC + lane + 32];
#pragma unroll
    for (int o = 16; o >= 1; o >>= 1) {
        s1 += __shfl_xor_sync(0xffffffffu, s1, o);
        s2 += __shfl_xor_sync(0xffffffffu, s2, o);
    }
    if (lane == 0) { ssrc[n * Hh + warp] = s1; sdst[n * Hh + warp] = s2; }
}

__device__ __forceinline__ float lrelu02(float x) { return x > 0.f ? x : 0.2f * x; }

// ---------------- GAT aggregation, H=8, shared-alpha ----------------
__global__ void k_agg8(const float* __restrict__ hbuf, const float* __restrict__ ssrc,
                       const float* __restrict__ sdst, const float* __restrict__ bias,
                       float* __restrict__ out) {
    int dstn = blockIdx.x;
    int tid = threadIdx.x;
    __shared__ float sh_sdst[HH], sh_m[HH], sh_sinv[HH];
    __shared__ float sh_alpha[32 * HH];
    __shared__ int   sh_src[32];
    if (tid < HH) sh_sdst[tid] = sdst[dstn * HH + tid];
    __syncthreads();
    int beg = g_rowptr[dstn], end = g_rowptr[dstn + 1];
    int warp = tid >> 5, lane = tid & 31;
    {
        int hh = warp * 2 + (lane >> 4);
        int sub = lane & 15;
        float sd = sh_sdst[hh];
        float mx = -3.4e38f;
        for (int i = beg + sub; i < end; i += 16)
            mx = fmaxf(mx, lrelu02(ssrc[g_csrc[i] * HH + hh] + sd));
#pragma unroll
        for (int o = 1; o < 16; o <<= 1) mx = fmaxf(mx, __shfl_xor_sync(0xffffffffu, mx, o));
        float se = 0.f;
        for (int i = beg + sub; i < end; i += 16)
            se += __expf(lrelu02(ssrc[g_csrc[i] * HH + hh] + sd) - mx);
#pragma unroll
        for (int o = 1; o < 16; o <<= 1) se += __shfl_xor_sync(0xffffffffu, se, o);
        if (sub == 0) { sh_m[hh] = mx; sh_sinv[hh] = 1.f / (se + 1e-16f); }
    }
    __syncthreads();
    int hh = tid >> 4;
    int c4 = (tid & 15) << 2;
    float4 acc = make_float4(0.f, 0.f, 0.f, 0.f);
    for (int c0 = beg; c0 < end; c0 += 32) {
        int cnt = min(32, end - c0);
        for (int t = tid; t < cnt * HH; t += 128) {
            int e = t >> 3, h2 = t & 7;
            int s = g_csrc[c0 + e];
            if (h2 == 0) sh_src[e] = s;
            sh_alpha[e * HH + h2] =
                __expf(lrelu02(ssrc[s * HH + h2] + sh_sdst[h2]) - sh_m[h2]) * sh_sinv[h2];
        }
        __syncthreads();
        for (int e = 0; e < cnt; e++) {
            float alpha = sh_alpha[e * HH + hh];
            float4 v = *(const float4*)(hbuf + (size_t)sh_src[e] * HC + hh * CC + c4);
            acc.x = fmaf(alpha, v.x, acc.x);
            acc.y = fmaf(alpha, v.y, acc.y);
            acc.z = fmaf(alpha, v.z, acc.z);
            acc.w = fmaf(alpha, v.w, acc.w);
        }
        __syncthreads();
    }
    float4 bb = *(const float4*)(bias + hh * CC + c4);
    acc.x += bb.x; acc.y += bb.y; acc.z += bb.z; acc.w += bb.w;
    *(float4*)(out + (size_t)dstn * HC + hh * CC + c4) = acc;
}

// ---------------- GAT aggregation, H=1 C=64, shared-alpha ----------------
__global__ void k_agg1(const float* __restrict__ h3, const float* __restrict__ ssrc,
                       const float* __restrict__ sdst, const float* __restrict__ bias,
                       float* __restrict__ out) {
    int dstn = blockIdx.x;
    int tid = threadIdx.x;
    __shared__ float sh_m, sh_sinv;
    __shared__ float sh_alpha[64];
    __shared__ int   sh_src[64];
    float sd = sdst[dstn];
    int beg = g_rowptr[dstn], end = g_rowptr[dstn + 1];
    if (tid < 32) {
        float mx = -3.4e38f;
        for (int i = beg + tid; i < end; i += 32)
            mx = fmaxf(mx, lrelu02(ssrc[g_csrc[i]] + sd));
#pragma unroll
        for (int o = 1; o < 32; o <<= 1) mx = fmaxf(mx, __shfl_xor_sync(0xffffffffu, mx, o));
        float se = 0.f;
        for (int i = beg + tid; i < end; i += 32)
            se += __expf(lrelu02(ssrc[g_csrc[i]] + sd) - mx);
#pragma unroll
        for (int o = 1; o < 32; o <<= 1) se += __shfl_xor_sync(0xffffffffu, se, o);
        if (tid == 0) { sh_m = mx; sh_sinv = 1.f / (se + 1e-16f); }
    }
    __syncthreads();
    float m = sh_m, sinv = sh_sinv;
    float acc = 0.f;
    for (int c0 = beg; c0 < end; c0 += 64) {
        int cnt = min(64, end - c0);
        if (tid < cnt) {
            int s = g_csrc[c0 + tid];
            sh_src[tid] = s;
            sh_alpha[tid] = __expf(lrelu02(ssrc[s] + sd) - m) * sinv;
        }
        __syncthreads();
        for (int e = 0; e < cnt; e++)
            acc = fmaf(sh_alpha[e], h3[(size_t)sh_src[e] * CC + tid], acc);
        __syncthreads();
    }
    out[(size_t)dstn * CC + tid] = acc + bias[tid];
}

// ---------------- BatchNorm (training stats), partial-sum version ----------------
__global__ void k_bnstats(const float* __restrict__ x, int Cdim, int rowsPerBlock) {
    int c = threadIdx.x;
    int b = blockIdx.x;
    int r0 = b * rowsPerBlock;
    int r1 = min(r0 + rowsPerBlock, NN);
    float s = 0.f, q = 0.f;
    for (int r = r0; r < r1; r++) {
        float v = x[(size_t)r * Cdim + c];
        s += v; q = fmaf(v, v, q);
    }
    g_bnpart[b * Cdim + c] = s;
    g_bnpart2[b * Cdim + c] = q;
}

__global__ void k_bnfinal(const float* __restrict__ g, const float* __restrict__ be, int Cdim) {
    int c = threadIdx.x;
    if (c >= Cdim) return;
    float s = 0.f, q = 0.f;
    for (int b = 0; b < NBN; b++) {
        s += g_bnpart[b * Cdim + c];
        q += g_bnpart2[b * Cdim + c];
    }
    float mu = s / (float)NN;
    float var = q / (float)NN - mu * mu;
    var = fmaxf(var, 0.f);
    float inv = rsqrtf(var + 1e-5f);
    float sc = g[c] * inv;
    g_scale[c] = sc;
    g_shift[c] = be[c] - sc * mu;
}

// out = res + elu(scale*in+shift); optional bf16 hi/lo split of out
__global__ void k_bnapply(const float* __restrict__ in, const float* __restrict__ res,
                          float* __restrict__ out,
                          __nv_bfloat16* __restrict__ outH, __nv_bfloat16* __restrict__ outL,
                          int Cdim, int doElu, int total4) {
    int i = blockIdx.x * blockDim.x + threadIdx.x;
    int stride = gridDim.x * blockDim.x;
    int c4cnt = Cdim >> 2;
    for (; i < total4; i += stride) {
        int c4 = (i % c4cnt) << 2;
        float4 v = ((const float4*)in)[i];
        float4 sc = *(const float4*)&g_scale[c4];
        float4 sh = *(const float4*)&g_shift[c4];
        float o0 = fmaf(sc.x, v.x, sh.x);
        float o1 = fmaf(sc.y, v.y, sh.y);
        float o2 = fmaf(sc.z, v.z, sh.z);
        float o3 = fmaf(sc.w, v.w, sh.w);
        if (doElu) {
            o0 = o0 > 0.f ? o0 : expm1f(o0);
            o1 = o1 > 0.f ? o1 : expm1f(o1);
            o2 = o2 > 0.f ? o2 : expm1f(o2);
            o3 = o3 > 0.f ? o3 : expm1f(o3);
        }
        if (res) {
            float4 rv = ((const float4*)res)[i];
            o0 += rv.x; o1 += rv.y; o2 += rv.z; o3 += rv.w;
        }
        ((float4*)out)[i] = make_float4(o0, o1, o2, o3);
        if (outH) {
            __nv_bfloat16 h0, h1, h2, h3, l0, l1, l2, l3;
            split_bf16(o0, h0, l0); split_bf16(o1, h1, l1);
            split_bf16(o2, h2, l2); split_bf16(o3, h3, l3);
            ((__nv_bfloat162*)outH)[2 * i]     = __halves2bfloat162(h0, h1);
            ((__nv_bfloat162*)outH)[2 * i + 1] = __halves2bfloat162(h2, h3);
            ((__nv_bfloat162*)outL)[2 * i]     = __halves2bfloat162(l0, l1);
            ((__nv_bfloat162*)outL)[2 * i + 1] = __halves2bfloat162(l2, l3);
        }
    }
}

// ---------------- pooling + classifier ----------------
__global__ void k_poolzero() {
    int i = threadIdx.x + blockIdx.x * blockDim.x;
    if (i < GG * CC) g_pool[i] = 0.f;
    if (i < GG) g_cntg[i] = 0.f;
}
__global__ void k_pool(const float* __restrict__ x3, const int* __restrict__ batch) {
    int n = blockIdx.x;
    int c = threadIdx.x;
    int g = batch[n];
    atomicAdd(&g_pool[g * CC + c], x3[(size_t)n * CC + c]);
    if (c == 0) atomicAdd(&g_cntg[g], 1.0f);
}
__global__ void k_final(const float* __restrict__ linW, const float* __restrict__ linb,
                        float* __restrict__ out) {
    int g = blockIdx.x;
    int j = threadIdx.x;
    __shared__ float xg[CC];
    float cv = fmaxf(g_cntg[g], 1.0f);
    xg[j] = g_pool[g * CC + j] / cv;
    __syncthreads();
    float acc = linb[j];
#pragma unroll
    for (int c = 0; c < CC; c++) acc = fmaf(xg[c], linW[c * NCLS + j], acc);
    out[g * NCLS + j] = acc;
}

// ---------------- host side ----------------
extern "C" void kernel_launch(void* const* d_in, const int* in_sizes, int n_in,
                              void* d_out, int out_size) {
    const float* x      = (const float*)d_in[0];
    const int*   ei     = (const int*)d_in[1];
    const int*   batch  = (const int*)d_in[2];
    const float* enc_W  = (const float*)d_in[3];
    const float* enc_b  = (const float*)d_in[4];
    const float* W1     = (const float*)d_in[5];
    const float* as1    = (const float*)d_in[6];
    const float* ad1    = (const float*)d_in[7];
    const float* b1     = (const float*)d_in[8];
    const float* g1     = (const float*)d_in[9];
    const float* be1    = (const float*)d_in[10];
    const float* W2     = (const float*)d_in[11];
    const float* as2    = (const float*)d_in[12];
    const float* ad2    = (const float*)d_in[13];
    const float* b2     = (const float*)d_in[14];
    const float* g2     = (const float*)d_in[15];
    const float* be2    = (const float*)d_in[16];
    const float* W3     = (const float*)d_in[17];
    const float* as3    = (const float*)d_in[18];
    const float* ad3    = (const float*)d_in[19];
    const float* b3     = (const float*)d_in[20];
    const float* g3     = (const float*)d_in[21];
    const float* be3    = (const float*)d_in[22];
    const float* linW   = (const float*)d_in[23];
    const float* linb   = (const float*)d_in[24];
    float* out = (float*)d_out;

    float *bufA, *bufB, *hbuf, *gat, *ssrc, *sdst, *x3, *gat3;
    __nv_bfloat16 *Ah, *Al, *Ah2, *Al2, *Wth, *Wtl;
    cudaGetSymbolAddress((void**)&bufA, g_bufA);
    cudaGetSymbolAddress((void**)&bufB, g_bufB);
    cudaGetSymbolAddress((void**)&hbuf, g_h);
    cudaGetSymbolAddress((void**)&gat,  g_gat);
    cudaGetSymbolAddress((void**)&ssrc, g_ssrc);
    cudaGetSymbolAddress((void**)&sdst, g_sdst);
    cudaGetSymbolAddress((void**)&x3,   g_x3);
    cudaGetSymbolAddress((void**)&gat3, g_gat3);
    cudaGetSymbolAddress((void**)&Ah,   g_Ah);
    cudaGetSymbolAddress((void**)&Al,   g_Al);
    cudaGetSymbolAddress((void**)&Ah2,  g_Ah2);
    cudaGetSymbolAddress((void**)&Al2,  g_Al2);
    cudaGetSymbolAddress((void**)&Wth,  g_Wth);
    cudaGetSymbolAddress((void**)&Wtl,  g_Wtl);

    cudaFuncSetAttribute(k_gemm_mma, cudaFuncAttributeMaxDynamicSharedMemorySize, SMEM_GEMM);

    // ---- CSR build ----
    k_zero_cnt<<<(NN + 255) / 256, 256>>>();
    k_count<<<(EE + 255) / 256, 256>>>(ei);
    k_scan<<<1, 1024>>>();
    k_fill_self<<<(NN + 255) / 256, 256>>>();
    k_fill<<<(EE + 255) / 256, 256>>>(ei);

    dim3 gGrid(HC / 64, (NN + 127) / 128);
    dim3 gGrid3(1, (NN + 127) / 128);
    dim3 wtGrid(HC / 32, HC / 32), wtBlk(32, 8);
    dim3 wtGrid3(CC / 32, HC / 32);
    const int A4 = NN * HC / 4;
    const int T4 = NN * HC / 4;
    const int T4c = NN * CC / 4;

    // ---- encoder: bufA = x @ enc_W + enc_b (writes split -> Ah2/Al2) ----
    k_cvt_act<<<512, 256>>>(x, Ah, Al, A4);
    k_cvt_wT<<<wtGrid, wtBlk>>>(enc_W, Wth, Wtl, HC, HC);
    k_gemm_mma<<<gGrid, 256, SMEM_GEMM>>>(Ah, Al, Wth, Wtl, enc_b, bufA, Ah2, Al2, NN, HC);

    // ---- layer 1 (input split Ah2/Al2; bnapply writes split -> Ah/Al) ----
    k_cvt_wT<<<wtGrid, wtBlk>>>(W1, Wth, Wtl, HC, HC);
    k_gemm_mma<<<gGrid, 256, SMEM_GEMM>>>(Ah2, Al2, Wth, Wtl, nullptr, hbuf, nullptr, nullptr, NN, HC);
    k_scores<<<NN, 32 * HH>>>(hbuf, as1, ad1, ssrc, sdst, HH);
    k_agg8<<<NN, 128>>>(hbuf, ssrc, sdst, b1, gat);
    k_bnstats<<<NBN, HC>>>(gat, HC, NN / NBN);
    k_bnfinal<<<1, HC>>>(g1, be1, HC);
    k_bnapply<<<512, 256>>>(gat, bufA, bufB, Ah, Al, HC, 1, T4);

    // ---- layer 2 (input split Ah/Al; bnapply writes split -> Ah2/Al2) ----
    k_cvt_wT<<<wtGrid, wtBlk>>>(W2, Wth, Wtl, HC, HC);
    k_gemm_mma<<<gGrid, 256, SMEM_GEMM>>>(Ah, Al, Wth, Wtl, nullptr, hbuf, nullptr, nullptr, NN, HC);
    k_scores<<<NN, 32 * HH>>>(hbuf, as2, ad2, ssrc, sdst, HH);
    k_agg8<<<NN, 128>>>(hbuf, ssrc, sdst, b2, gat);
    k_bnstats<<<NBN, HC>>>(gat, HC, NN / NBN);
    k_bnfinal<<<1, HC>>>(g2, be2, HC);
    k_bnapply<<<512, 256>>>(gat, bufB, bufA, Ah2, Al2, HC, 1, T4);

    // ---- layer 3 (H=1, C=64; input split Ah2/Al2) ----
    k_cvt_wT<<<wtGrid3, wtBlk>>>(W3, Wth, Wtl, HC, CC);
    k_gemm_mma<<<gGrid3, 256, SMEM_GEMM>>>(Ah2, Al2, Wth, Wtl, nullptr, x3, nullptr, nullptr, NN, CC);
    k_scores<<<NN, 32>>>(x3, as3, ad3, ssrc, sdst, 1);
    k_agg1<<<NN, 64>>>(x3, ssrc, sdst, b3, gat3);
    k_bnstats<<<NBN, CC>>>(gat3, CC, NN / NBN);
    k_bnfinal<<<1, CC>>>(g3, be3, CC);
    k_bnapply<<<256, 256>>>(gat3, nullptr, x3, nullptr, nullptr, CC, 0, T4c);

    // ---- pool + classifier ----
    k_poolzero<<<(GG * CC + 255) / 256, 256>>>();
    k_pool<<<NN, CC>>>(x3, batch);
    k_final<<<GG, NCLS>>>(linW, linb, out);
}

// round 8
// speedup vs baseline: 2.1033x; 1.0227x over previous
#include <cuda_runtime.h>
#include <cuda_bf16.h>
#include <math.h>
#include <stdint.h>

// Problem constants
#define NN    10000
#define EE    160000
#define EP    170000
#define HH    8
#define CC    64
#define HC    512
#define GG    64
#define NCLS  64
#define NBN   100            // bn partial blocks

// ---------------- device scratch ----------------
__device__ float g_bufA[NN * HC];
__device__ float g_bufB[NN * HC];
__device__ float g_h[NN * HC];
__device__ float g_gat[NN * HC];
__device__ float g_ssrc[NN * HH];
__device__ float g_sdst[NN * HH];
__device__ float g_x3[NN * CC];
__device__ float g_gat3[NN * CC];
__device__ int   g_rowptr[NN + 1];
__device__ int   g_cnt[NN];
__device__ int   g_csrc[EP];
__device__ float g_bnpart[NBN * HC];
__device__ float g_bnpart2[NBN * HC];
__device__ float g_scale[HC];
__device__ float g_shift[HC];
__device__ __nv_bfloat16 g_Ah[NN * HC];
__device__ __nv_bfloat16 g_Al[NN * HC];
__device__ __nv_bfloat16 g_Ah2[NN * HC];
__device__ __nv_bfloat16 g_Al2[NN * HC];
__device__ __nv_bfloat16 g_WthA[4][HC * HC];   // transposed weight hi [N,K], per layer
__device__ __nv_bfloat16 g_WtlA[4][HC * HC];   // transposed weight lo

// ======================= helpers =======================
__device__ __forceinline__ uint32_t smem_to_u32(const void* p) {
    uint32_t a;
    asm("{ .reg .u64 t; cvta.to.shared.u64 t, %1; cvt.u32.u64 %0, t; }" : "=r"(a) : "l"(p));
    return a;
}
__device__ __forceinline__ void ldm_x4(uint32_t* r, uint32_t addr) {
    asm volatile("ldmatrix.sync.aligned.m8n8.x4.shared.b16 {%0,%1,%2,%3}, [%4];"
                 : "=r"(r[0]), "=r"(r[1]), "=r"(r[2]), "=r"(r[3]) : "r"(addr));
}
__device__ __forceinline__ void mma16816(float* c, const uint32_t* a, const uint32_t* b) {
    asm volatile(
        "mma.sync.aligned.m16n8k16.row.col.f32.bf16.bf16.f32 "
        "{%0,%1,%2,%3}, {%4,%5,%6,%7}, {%8,%9}, {%0,%1,%2,%3};"
        : "+f"(c[0]), "+f"(c[1]), "+f"(c[2]), "+f"(c[3])
        : "r"(a[0]), "r"(a[1]), "r"(a[2]), "r"(a[3]), "r"(b[0]), "r"(b[1]));
}
__device__ __forceinline__ void cp16(uint32_t dst, const void* src, int sz) {
    asm volatile("cp.async.cg.shared.global [%0], [%1], 16, %2;"
                 :: "r"(dst), "l"(src), "r"(sz));
}
#define CP_COMMIT() asm volatile("cp.async.commit_group;" ::: "memory")
#define CP_WAIT(n)  asm volatile("cp.async.wait_group %0;" :: "n"(n) : "memory")

__device__ __forceinline__ void split_bf16(float v, __nv_bfloat16& h, __nv_bfloat16& l) {
    h = __float2bfloat16(v);
    l = __float2bfloat16(v - __bfloat162float(h));
}

// ======================= prep mega-kernel =======================
// grid (16,16,6), block (32,8)
//   z=0..3 : transpose+split weight z into g_WthA[z]/g_WtlA[z]  (W[K,Nn] -> Wt[Nn,K])
//   z=4    : zero g_cnt
//   z=5    : split input activations x -> Ah/Al
__global__ void k_prep(const float* __restrict__ x,
                       __nv_bfloat16* __restrict__ Ah, __nv_bfloat16* __restrict__ Al,
                       const float* __restrict__ W0, const float* __restrict__ W1,
                       const float* __restrict__ W2, const float* __restrict__ W3) {
    int z = blockIdx.z;
    int tx = threadIdx.x, ty = threadIdx.y;
    int tid = ty * 32 + tx;
    if (z < 4) {
        const float* W = (z == 0) ? W0 : (z == 1) ? W1 : (z == 2) ? W2 : W3;
        int Nn = (z == 3) ? CC : HC;
        int bx = blockIdx.x * 32;
        int by = blockIdx.y * 32;
        if (bx >= Nn) return;
        __shared__ float t[32][33];
#pragma unroll
        for (int j = 0; j < 32; j += 8)
            t[ty + j][tx] = W[(size_t)(by + ty + j) * Nn + bx + tx];
        __syncthreads();
        __nv_bfloat16* th = g_WthA[z];
        __nv_bfloat16* tl = g_WtlA[z];
#pragma unroll
        for (int j = 0; j < 32; j += 8) {
            float v = t[tx][ty + j];
            __nv_bfloat16 h, l;
            split_bf16(v, h, l);
            size_t o = (size_t)(bx + ty + j) * HC + by + tx;
            th[o] = h; tl[o] = l;
        }
    } else if (z == 4) {
        int i = (blockIdx.y * 16 + blockIdx.x) * 256 + tid;
        if (i < NN) g_cnt[i] = 0;
    } else {
        const int n4 = NN * HC / 4;
        int i = (blockIdx.y * 16 + blockIdx.x) * 256 + tid;
        for (; i < n4; i += 256 * 256) {
            float4 v = ((const float4*)x)[i];
            __nv_bfloat16 h0, h1, h2, h3, l0, l1, l2, l3;
            split_bf16(v.x, h0, l0); split_bf16(v.y, h1, l1);
            split_bf16(v.z, h2, l2); split_bf16(v.w, h3, l3);
            ((__nv_bfloat162*)Ah)[2 * i]     = __halves2bfloat162(h0, h1);
            ((__nv_bfloat162*)Ah)[2 * i + 1] = __halves2bfloat162(h2, h3);
            ((__nv_bfloat162*)Al)[2 * i]     = __halves2bfloat162(l0, l1);
            ((__nv_bfloat162*)Al)[2 * i + 1] = __halves2bfloat162(l2, l3);
        }
    }
}

// ======================= cp.async double-buffered warp-MMA GEMM =======================
#define AH_OFF 0
#define AL_OFF 16384
#define BH_OFF 32768
#define BL_OFF 40960
#define STG    49152
#define SMEM_GEMM (2 * STG)

__global__ __launch_bounds__(256, 2)
void k_gemm_mma(const __nv_bfloat16* __restrict__ Ah, const __nv_bfloat16* __restrict__ Al,
                const __nv_bfloat16* __restrict__ Bh, const __nv_bfloat16* __restrict__ Bl,
                const float* __restrict__ bias, float* __restrict__ Cm,
                __nv_bfloat16* __restrict__ outH, __nv_bfloat16* __restrict__ outL,
                int M, int Nn) {
    extern __shared__ char smem[];
    const uint32_t sb = smem_to_u32(smem);
    const int tid = threadIdx.x;
    const int lane = tid & 31;
    const int wid = tid >> 5;
    const int warpM = wid & 3;
    const int warpN = wid >> 2;
    const int bm = blockIdx.y * 128;
    const int bn = blockIdx.x * 64;

    float acc[2][4][4];
#pragma unroll
    for (int mt = 0; mt < 2; mt++)
#pragma unroll
        for (int nt = 0; nt < 4; nt++)
#pragma unroll
            for (int r = 0; r < 4; r++) acc[mt][nt][r] = 0.f;

    auto issue = [&](int kb, int buf) {
        const uint32_t sbase = sb + buf * STG;
#pragma unroll
        for (int it = 0; it < 4; it++) {
            int idx = tid + it * 256;
            int r = idx >> 3, c16 = idx & 7;
            uint32_t so = (uint32_t)(r * 128 + c16 * 16);
            so ^= (so >> 3) & 0x70;
            int gr = bm + r;
            int grc = gr < M ? gr : 0;
            int sz = gr < M ? 16 : 0;
            size_t goff = (size_t)grc * 512 + kb * 64 + c16 * 8;
            cp16(sbase + AH_OFF + so, Ah + goff, sz);
            cp16(sbase + AL_OFF + so, Al + goff, sz);
        }
#pragma unroll
        for (int it = 0; it < 2; it++) {
            int idx = tid + it * 256;
            int r = idx >> 3, c16 = idx & 7;
            uint32_t so = (uint32_t)(r * 128 + c16 * 16);
            so ^= (so >> 3) & 0x70;
            size_t goff = (size_t)(bn + r) * 512 + kb * 64 + c16 * 8;
            cp16(sbase + BH_OFF + so, Bh + goff, 16);
            cp16(sbase + BL_OFF + so, Bl + goff, 16);
        }
    };

    const uint32_t aRow = (uint32_t)(warpM * 32 + (lane & 15));
    const uint32_t aC16b = (uint32_t)(lane >> 4);
    const uint32_t bRow = (uint32_t)(warpN * 32 + ((lane >> 4) << 3) + (lane & 7));
    const uint32_t bC16b = (uint32_t)((lane >> 3) & 1);

    issue(0, 0);
    CP_COMMIT();

    for (int kb = 0; kb < 8; kb++) {
        if (kb + 1 < 8) { issue(kb + 1, (kb + 1) & 1); CP_COMMIT(); }
        if (kb + 1 < 8) { CP_WAIT(1); } else { CP_WAIT(0); }
        __syncthreads();
        const uint32_t sbase = sb + (kb & 1) * STG;
#pragma unroll
        for (int ks = 0; ks < 4; ks++) {
            uint32_t ah[2][4], al[2][4], bh[2][4], bl[2][4];
            uint32_t ac16 = (uint32_t)(ks * 2) + aC16b;
#pragma unroll
            for (int mt = 0; mt < 2; mt++) {
                uint32_t off = (aRow + mt * 16) * 128 + ac16 * 16;
                off ^= (off >> 3) & 0x70;
                ldm_x4(ah[mt], sbase + AH_OFF + off);
                ldm_x4(al[mt], sbase + AL_OFF + off);
            }
            uint32_t bc16 = (uint32_t)(ks * 2) + bC16b;
#pragma unroll
            for (int half = 0; half < 2; half++) {
                uint32_t off = (bRow + half * 16) * 128 + bc16 * 16;
                off ^= (off >> 3) & 0x70;
                ldm_x4(bh[half], sbase + BH_OFF + off);
                ldm_x4(bl[half], sbase + BL_OFF + off);
            }
#pragma unroll
            for (int mt = 0; mt < 2; mt++) {
#pragma unroll
                for (int nt = 0; nt < 4; nt++) {
                    const uint32_t* bhf = &bh[nt >> 1][(nt & 1) * 2];
                    const uint32_t* blf = &bl[nt >> 1][(nt & 1) * 2];
                    mma16816(acc[mt][nt], ah[mt], bhf);
                    mma16816(acc[mt][nt], al[mt], bhf);
                    mma16816(acc[mt][nt], ah[mt], blf);
                }
            }
        }
        __syncthreads();
    }

    const int rowBase = bm + warpM * 32 + (lane >> 2);
    const int colBase = bn + warpN * 32 + (lane & 3) * 2;
#pragma unroll
    for (int mt = 0; mt < 2; mt++) {
#pragma unroll
        for (int nt = 0; nt < 4; nt++) {
            int gc = colBase + nt * 8;
            float b0 = 0.f, b1 = 0.f;
            if (bias) { b0 = bias[gc]; b1 = bias[gc + 1]; }
#pragma unroll
            for (int half = 0; half < 2; half++) {
                int r = rowBase + mt * 16 + half * 8;
                if (r < M) {
                    float v0 = acc[mt][nt][half * 2] + b0;
                    float v1 = acc[mt][nt][half * 2 + 1] + b1;
                    *(float2*)(Cm + (size_t)r * Nn + gc) = make_float2(v0, v1);
                    if (outH) {
                        __nv_bfloat16 h0, h1, l0, l1;
                        split_bf16(v0, h0, l0);
                        split_bf16(v1, h1, l1);
                        *(__nv_bfloat162*)(outH + (size_t)r * Nn + gc) = __halves2bfloat162(h0, h1);
                        *(__nv_bfloat162*)(outL + (size_t)r * Nn + gc) = __halves2bfloat162(l0, l1);
                    }
                }
            }
        }
    }
}

// ---------------- CSR build ----------------
__global__ void k_count(const int* __restrict__ ei) {
    int e = blockIdx.x * blockDim.x + threadIdx.x;
    if (e < EE) atomicAdd(&g_cnt[ei[EE + e]], 1);
}
__global__ void k_scan() {
    __shared__ int sh[1024];
    __shared__ int carry;
    int tid = threadIdx.x;
    if (tid == 0) carry = 0;
    __syncthreads();
    for (int base = 0; base < NN; base += 1024) {
        int i = base + tid;
        int v = (i < NN) ? (g_cnt[i] + 1) : 0;
        sh[tid] = v;
        __syncthreads();
        for (int off = 1; off < 1024; off <<= 1) {
            int t = (tid >= off) ? sh[tid - off] : 0;
            __syncthreads();
            sh[tid] += t;
            __syncthreads();
        }
        if (i < NN) g_rowptr[i + 1] = carry + sh[tid];
        __syncthreads();
        if (tid == 1023) carry += sh[1023];
        __syncthreads();
    }
    if (tid == 0) g_rowptr[0] = 0;
}
__global__ void k_fill_self() {
    int i = blockIdx.x * blockDim.x + threadIdx.x;
    if (i < NN) {
        int rp = g_rowptr[i];
        g_csrc[rp] = i;
        g_cnt[i] = rp + 1;
    }
}
__global__ void k_fill(const int* __restrict__ ei) {
    int e = blockIdx.x * blockDim.x + threadIdx.x;
    if (e < EE) {
        int dst = ei[EE + e];
        int slot = atomicAdd(&g_cnt[dst], 1);
        g_csrc[slot] = ei[e];
    }
}

// ---------------- attention score precompute ----------------
__global__ void k_scores(const float* __restrict__ h, const float* __restrict__ a_s,
                         const float* __restrict__ a_d, float* __restrict__ ssrc,
                         float* __restrict__ sdst, int Hh) {
    int n = blockIdx.x;
    int warp = threadIdx.x >> 5, lane = threadIdx.x & 31;
    const float* hp = h + (size_t)n * Hh * CC + warp * CC;
    float v0 = hp[lane], v1 = hp[lane + 32];
    float s1 = v0 * a_s[warp * CC + lane] + v1 * a_s[warp * CC + lane + 32];
    float s2 = v0 * a_d[warp * CC + lane] + v1 * a_d[warp * CC + lane + 32];
#pragma unroll
    for (int o = 16; o >= 1; o >>= 1) {
        s1 += __shfl_xor_sync(0xffffffffu, s1, o);
        s2 += __shfl_xor_sync(0xffffffffu, s2, o);
    }
    if (lane == 0) { ssrc[n * Hh + warp] = s1; sdst[n * Hh + warp] = s2; }
}

__device__ __forceinline__ float lrelu02(float x) { return x > 0.f ? x : 0.2f * x; }

// ---------------- GAT aggregation, H=8, shared-alpha ----------------
__global__ void k_agg8(const float* __restrict__ hbuf, const float* __restrict__ ssrc,
                       const float* __restrict__ sdst, const float* __restrict__ bias,
                       float* __restrict__ out) {
    int dstn = blockIdx.x;
    int tid = threadIdx.x;
    __shared__ float sh_sdst[HH], sh_m[HH], sh_sinv[HH];
    __shared__ float sh_alpha[32 * HH];
    __shared__ int   sh_src[32];
    if (tid < HH) sh_sdst[tid] = sdst[dstn * HH + tid];
    __syncthreads();
    int beg = g_rowptr[dstn], end = g_rowptr[dstn + 1];
    int warp = tid >> 5, lane = tid & 31;
    {
        int hh = warp * 2 + (lane >> 4);
        int sub = lane & 15;
        float sd = sh_sdst[hh];
        float mx = -3.4e38f;
        for (int i = beg + sub; i < end; i += 16)
            mx = fmaxf(mx, lrelu02(ssrc[g_csrc[i] * HH + hh] + sd));
#pragma unroll
        for (int o = 1; o < 16; o <<= 1) mx = fmaxf(mx, __shfl_xor_sync(0xffffffffu, mx, o));
        float se = 0.f;
        for (int i = beg + sub; i < end; i += 16)
            se += __expf(lrelu02(ssrc[g_csrc[i] * HH + hh] + sd) - mx);
#pragma unroll
        for (int o = 1; o < 16; o <<= 1) se += __shfl_xor_sync(0xffffffffu, se, o);
        if (sub == 0) { sh_m[hh] = mx; sh_sinv[hh] = 1.f / (se + 1e-16f); }
    }
    __syncthreads();
    int hh = tid >> 4;
    int c4 = (tid & 15) << 2;
    float4 acc = make_float4(0.f, 0.f, 0.f, 0.f);
    for (int c0 = beg; c0 < end; c0 += 32) {
        int cnt = min(32, end - c0);
        for (int t = tid; t < cnt * HH; t += 128) {
            int e = t >> 3, h2 = t & 7;
            int s = g_csrc[c0 + e];
            if (h2 == 0) sh_src[e] = s;
            sh_alpha[e * HH + h2] =
                __expf(lrelu02(ssrc[s * HH + h2] + sh_sdst[h2]) - sh_m[h2]) * sh_sinv[h2];
        }
        __syncthreads();
        for (int e = 0; e < cnt; e++) {
            float alpha = sh_alpha[e * HH + hh];
            float4 v = *(const float4*)(hbuf + (size_t)sh_src[e] * HC + hh * CC + c4);
            acc.x = fmaf(alpha, v.x, acc.x);
            acc.y = fmaf(alpha, v.y, acc.y);
            acc.z = fmaf(alpha, v.z, acc.z);
            acc.w = fmaf(alpha, v.w, acc.w);
        }
        __syncthreads();
    }
    float4 bb = *(const float4*)(bias + hh * CC + c4);
    acc.x += bb.x; acc.y += bb.y; acc.z += bb.z; acc.w += bb.w;
    *(float4*)(out + (size_t)dstn * HC + hh * CC + c4) = acc;
}

// ---------------- GAT aggregation, H=1 C=64, shared-alpha ----------------
__global__ void k_agg1(const float* __restrict__ h3, const float* __restrict__ ssrc,
                       const float* __restrict__ sdst, const float* __restrict__ bias,
                       float* __restrict__ out) {
    int dstn = blockIdx.x;
    int tid = threadIdx.x;
    __shared__ float sh_m, sh_sinv;
    __shared__ float sh_alpha[64];
    __shared__ int   sh_src[64];
    float sd = sdst[dstn];
    int beg = g_rowptr[dstn], end = g_rowptr[dstn + 1];
    if (tid < 32) {
        float mx = -3.4e38f;
        for (int i = beg + tid; i < end; i += 32)
            mx = fmaxf(mx, lrelu02(ssrc[g_csrc[i]] + sd));
#pragma unroll
        for (int o = 1; o < 32; o <<= 1) mx = fmaxf(mx, __shfl_xor_sync(0xffffffffu, mx, o));
        float se = 0.f;
        for (int i = beg + tid; i < end; i += 32)
            se += __expf(lrelu02(ssrc[g_csrc[i]] + sd) - mx);
#pragma unroll
        for (int o = 1; o < 32; o <<= 1) se += __shfl_xor_sync(0xffffffffu, se, o);
        if (tid == 0) { sh_m = mx; sh_sinv = 1.f / (se + 1e-16f); }
    }
    __syncthreads();
    float m = sh_m, sinv = sh_sinv;
    float acc = 0.f;
    for (int c0 = beg; c0 < end; c0 += 64) {
        int cnt = min(64, end - c0);
        if (tid < cnt) {
            int s = g_csrc[c0 + tid];
            sh_src[tid] = s;
            sh_alpha[tid] = __expf(lrelu02(ssrc[s] + sd) - m) * sinv;
        }
        __syncthreads();
        for (int e = 0; e < cnt; e++)
            acc = fmaf(sh_alpha[e], h3[(size_t)sh_src[e] * CC + tid], acc);
        __syncthreads();
    }
    out[(size_t)dstn * CC + tid] = acc + bias[tid];
}

// ---------------- BatchNorm (training stats) ----------------
__global__ void k_bnstats(const float* __restrict__ x, int Cdim, int rowsPerBlock) {
    int c = threadIdx.x;
    int b = blockIdx.x;
    int r0 = b * rowsPerBlock;
    int r1 = min(r0 + rowsPerBlock, NN);
    float s = 0.f, q = 0.f;
    for (int r = r0; r < r1; r++) {
        float v = x[(size_t)r * Cdim + c];
        s += v; q = fmaf(v, v, q);
    }
    g_bnpart[b * Cdim + c] = s;
    g_bnpart2[b * Cdim + c] = q;
}

__global__ void k_bnfinal(const float* __restrict__ g, const float* __restrict__ be, int Cdim) {
    int c = threadIdx.x;
    if (c >= Cdim) return;
    float s = 0.f, q = 0.f;
    for (int b = 0; b < NBN; b++) {
        s += g_bnpart[b * Cdim + c];
        q += g_bnpart2[b * Cdim + c];
    }
    float mu = s / (float)NN;
    float var = q / (float)NN - mu * mu;
    var = fmaxf(var, 0.f);
    float inv = rsqrtf(var + 1e-5f);
    float sc = g[c] * inv;
    g_scale[c] = sc;
    g_shift[c] = be[c] - sc * mu;
}

__global__ void k_bnapply(const float* __restrict__ in, const float* __restrict__ res,
                          float* __restrict__ out,
                          __nv_bfloat16* __restrict__ outH, __nv_bfloat16* __restrict__ outL,
                          int Cdim, int doElu, int total4) {
    int i = blockIdx.x * blockDim.x + threadIdx.x;
    int stride = gridDim.x * blockDim.x;
    int c4cnt = Cdim >> 2;
    for (; i < total4; i += stride) {
        int c4 = (i % c4cnt) << 2;
        float4 v = ((const float4*)in)[i];
        float4 sc = *(const float4*)&g_scale[c4];
        float4 sh = *(const float4*)&g_shift[c4];
        float o0 = fmaf(sc.x, v.x, sh.x);
        float o1 = fmaf(sc.y, v.y, sh.y);
        float o2 = fmaf(sc.z, v.z, sh.z);
        float o3 = fmaf(sc.w, v.w, sh.w);
        if (doElu) {
            o0 = o0 > 0.f ? o0 : expm1f(o0);
            o1 = o1 > 0.f ? o1 : expm1f(o1);
            o2 = o2 > 0.f ? o2 : expm1f(o2);
            o3 = o3 > 0.f ? o3 : expm1f(o3);
        }
        if (res) {
            float4 rv = ((const float4*)res)[i];
            o0 += rv.x; o1 += rv.y; o2 += rv.z; o3 += rv.w;
        }
        ((float4*)out)[i] = make_float4(o0, o1, o2, o3);
        if (outH) {
            __nv_bfloat16 h0, h1, h2, h3, l0, l1, l2, l3;
            split_bf16(o0, h0, l0); split_bf16(o1, h1, l1);
            split_bf16(o2, h2, l2); split_bf16(o3, h3, l3);
            ((__nv_bfloat162*)outH)[2 * i]     = __halves2bfloat162(h0, h1);
            ((__nv_bfloat162*)outH)[2 * i + 1] = __halves2bfloat162(h2, h3);
            ((__nv_bfloat162*)outL)[2 * i]     = __halves2bfloat162(l0, l1);
            ((__nv_bfloat162*)outL)[2 * i + 1] = __halves2bfloat162(l2, l3);
        }
    }
}

// ---------------- fused pool + classifier (batch is sorted) ----------------
__global__ void k_poolfinal(const float* __restrict__ x3, const int* __restrict__ batch,
                            const float* __restrict__ linW, const float* __restrict__ linb,
                            float* __restrict__ out) {
    int g = blockIdx.x;
    int j = threadIdx.x;
    __shared__ float xg[CC];
    // binary search for [beg, end) of graph g
    int lo = 0, hi = NN;
    while (lo < hi) { int mid = (lo + hi) >> 1; if (batch[mid] < g) lo = mid + 1; else hi = mid; }
    int beg = lo;
    hi = NN;
    while (lo < hi) { int mid = (lo + hi) >> 1; if (batch[mid] <= g) lo = mid + 1; else hi = mid; }
    int end = lo;
    float s = 0.f;
    for (int n = beg; n < end; n++) s += x3[(size_t)n * CC + j];
    float cv = fmaxf((float)(end - beg), 1.0f);
    xg[j] = s / cv;
    __syncthreads();
    float acc = linb[j];
#pragma unroll
    for (int c = 0; c < CC; c++) acc = fmaf(xg[c], linW[c * NCLS + j], acc);
    out[g * NCLS + j] = acc;
}

// ---------------- host side ----------------
extern "C" void kernel_launch(void* const* d_in, const int* in_sizes, int n_in,
                              void* d_out, int out_size) {
    const float* x      = (const float*)d_in[0];
    const int*   ei     = (const int*)d_in[1];
    const int*   batch  = (const int*)d_in[2];
    const float* enc_W  = (const float*)d_in[3];
    const float* enc_b  = (const float*)d_in[4];
    const float* W1     = (const float*)d_in[5];
    const float* as1    = (const float*)d_in[6];
    const float* ad1    = (const float*)d_in[7];
    const float* b1     = (const float*)d_in[8];
    const float* g1     = (const float*)d_in[9];
    const float* be1    = (const float*)d_in[10];
    const float* W2     = (const float*)d_in[11];
    const float* as2    = (const float*)d_in[12];
    const float* ad2    = (const float*)d_in[13];
    const float* b2     = (const float*)d_in[14];
    const float* g2     = (const float*)d_in[15];
    const float* be2    = (const float*)d_in[16];
    const float* W3     = (const float*)d_in[17];
    const float* as3    = (const float*)d_in[18];
    const float* ad3    = (const float*)d_in[19];
    const float* b3     = (const float*)d_in[20];
    const float* g3     = (const float*)d_in[21];
    const float* be3    = (const float*)d_in[22];
    const float* linW   = (const float*)d_in[23];
    const float* linb   = (const float*)d_in[24];
    float* out = (float*)d_out;

    float *bufA, *bufB, *hbuf, *gat, *ssrc, *sdst, *x3, *gat3;
    __nv_bfloat16 *Ah, *Al, *Ah2, *Al2, *Wth, *Wtl;
    cudaGetSymbolAddress((void**)&bufA, g_bufA);
    cudaGetSymbolAddress((void**)&bufB, g_bufB);
    cudaGetSymbolAddress((void**)&hbuf, g_h);
    cudaGetSymbolAddress((void**)&gat,  g_gat);
    cudaGetSymbolAddress((void**)&ssrc, g_ssrc);
    cudaGetSymbolAddress((void**)&sdst, g_sdst);
    cudaGetSymbolAddress((void**)&x3,   g_x3);
    cudaGetSymbolAddress((void**)&gat3, g_gat3);
    cudaGetSymbolAddress((void**)&Ah,   g_Ah);
    cudaGetSymbolAddress((void**)&Al,   g_Al);
    cudaGetSymbolAddress((void**)&Ah2,  g_Ah2);
    cudaGetSymbolAddress((void**)&Al2,  g_Al2);
    cudaGetSymbolAddress((void**)&Wth,  g_WthA);
    cudaGetSymbolAddress((void**)&Wtl,  g_WtlA);
    __nv_bfloat16 *Wth0 = Wth,              *Wtl0 = Wtl;
    __nv_bfloat16 *Wth1 = Wth + HC * HC,    *Wtl1 = Wtl + HC * HC;
    __nv_bfloat16 *Wth2 = Wth + 2 * HC * HC,*Wtl2 = Wtl + 2 * HC * HC;
    __nv_bfloat16 *Wth3 = Wth + 3 * HC * HC,*Wtl3 = Wtl + 3 * HC * HC;

    cudaFuncSetAttribute(k_gemm_mma, cudaFuncAttributeMaxDynamicSharedMemorySize, SMEM_GEMM);

    dim3 gGrid(HC / 64, (NN + 127) / 128);
    dim3 gGrid3(1, (NN + 127) / 128);
    const int T4 = NN * HC / 4;
    const int T4c = NN * CC / 4;

    // ---- prep: all weight transposes + input split + cnt zero, one launch ----
    k_prep<<<dim3(16, 16, 6), dim3(32, 8)>>>(x, Ah, Al, enc_W, W1, W2, W3);

    // ---- CSR build ----
    k_count<<<(EE + 255) / 256, 256>>>(ei);
    k_scan<<<1, 1024>>>();
    k_fill_self<<<(NN + 255) / 256, 256>>>();
    k_fill<<<(EE + 255) / 256, 256>>>(ei);

    // ---- encoder ----
    k_gemm_mma<<<gGrid, 256, SMEM_GEMM>>>(Ah, Al, Wth0, Wtl0, enc_b, bufA, Ah2, Al2, NN, HC);

    // ---- layer 1 ----
    k_gemm_mma<<<gGrid, 256, SMEM_GEMM>>>(Ah2, Al2, Wth1, Wtl1, nullptr, hbuf, nullptr, nullptr, NN, HC);
    k_scores<<<NN, 32 * HH>>>(hbuf, as1, ad1, ssrc, sdst, HH);
    k_agg8<<<NN, 128>>>(hbuf, ssrc, sdst, b1, gat);
    k_bnstats<<<NBN, HC>>>(gat, HC, NN / NBN);
    k_bnfinal<<<1, HC>>>(g1, be1, HC);
    k_bnapply<<<512, 256>>>(gat, bufA, bufB, Ah, Al, HC, 1, T4);

    // ---- layer 2 ----
    k_gemm_mma<<<gGrid, 256, SMEM_GEMM>>>(Ah, Al, Wth2, Wtl2, nullptr, hbuf, nullptr, nullptr, NN, HC);
    k_scores<<<NN, 32 * HH>>>(hbuf, as2, ad2, ssrc, sdst, HH);
    k_agg8<<<NN, 128>>>(hbuf, ssrc, sdst, b2, gat);
    k_bnstats<<<NBN, HC>>>(gat, HC, NN / NBN);
    k_bnfinal<<<1, HC>>>(g2, be2, HC);
    k_bnapply<<<512, 256>>>(gat, bufB, bufA, Ah2, Al2, HC, 1, T4);

    // ---- layer 3 ----
    k_gemm_mma<<<gGrid3, 256, SMEM_GEMM>>>(Ah2, Al2, Wth3, Wtl3, nullptr, x3, nullptr, nullptr, NN, CC);
    k_scores<<<NN, 32>>>(x3, as3, ad3, ssrc, sdst, 1);
    k_agg1<<<NN, 64>>>(x3, ssrc, sdst, b3, gat3);
    k_bnstats<<<NBN, CC>>>(gat3, CC, NN / NBN);
    k_bnfinal<<<1, CC>>>(g3, be3, CC);
    k_bnapply<<<256, 256>>>(gat3, nullptr, x3, nullptr, nullptr, CC, 0, T4c);

    // ---- fused pool + classifier ----
    k_poolfinal<<<GG, NCLS>>>(x3, batch, linW, linb, out);
}

// round 10
// speedup vs baseline: 2.1370x; 1.0160x over previous
#include <cuda_runtime.h>
#include <cuda_bf16.h>
#include <math.h>
#include <stdint.h>

// Problem constants
#define NN    10000
#define EE    160000
#define EP    170000
#define HH    8
#define CC    64
#define HC    512
#define GG    64
#define NCLS  64
#define NBN   100            // bn partial blocks

// ---------------- device scratch ----------------
__device__ float g_bufA[NN * HC];
__device__ float g_bufB[NN * HC];
__device__ float g_h[NN * HC];
__device__ float g_gat[NN * HC];
__device__ float g_ssrc[NN * HH];
__device__ float g_sdst[NN * HH];
__device__ float g_x3[NN * CC];
__device__ float g_gat3[NN * CC];
__device__ int   g_rowptr[NN + 1];
__device__ int   g_cnt[NN];
__device__ int   g_csrc[EP];
__device__ float g_bnpart[NBN * HC];
__device__ float g_bnpart2[NBN * HC];
__device__ float g_scale[HC];
__device__ float g_shift[HC];
__device__ __nv_bfloat16 g_Ah[NN * HC];
__device__ __nv_bfloat16 g_Al[NN * HC];
__device__ __nv_bfloat16 g_Ah2[NN * HC];
__device__ __nv_bfloat16 g_Al2[NN * HC];
__device__ __nv_bfloat16 g_WthA[4][HC * HC];   // transposed weight hi [N,K], per layer
__device__ __nv_bfloat16 g_WtlA[4][HC * HC];   // transposed weight lo

// ======================= helpers =======================
__device__ __forceinline__ uint32_t smem_to_u32(const void* p) {
    uint32_t a;
    asm("{ .reg .u64 t; cvta.to.shared.u64 t, %1; cvt.u32.u64 %0, t; }" : "=r"(a) : "l"(p));
    return a;
}
__device__ __forceinline__ void ldm_x4(uint32_t* r, uint32_t addr) {
    asm volatile("ldmatrix.sync.aligned.m8n8.x4.shared.b16 {%0,%1,%2,%3}, [%4];"
                 : "=r"(r[0]), "=r"(r[1]), "=r"(r[2]), "=r"(r[3]) : "r"(addr));
}
__device__ __forceinline__ void mma16816(float* c, const uint32_t* a, const uint32_t* b) {
    asm volatile(
        "mma.sync.aligned.m16n8k16.row.col.f32.bf16.bf16.f32 "
        "{%0,%1,%2,%3}, {%4,%5,%6,%7}, {%8,%9}, {%0,%1,%2,%3};"
        : "+f"(c[0]), "+f"(c[1]), "+f"(c[2]), "+f"(c[3])
        : "r"(a[0]), "r"(a[1]), "r"(a[2]), "r"(a[3]), "r"(b[0]), "r"(b[1]));
}
__device__ __forceinline__ void cp16(uint32_t dst, const void* src, int sz) {
    asm volatile("cp.async.cg.shared.global [%0], [%1], 16, %2;"
                 :: "r"(dst), "l"(src), "r"(sz));
}
#define CP_COMMIT() asm volatile("cp.async.commit_group;" ::: "memory")
#define CP_WAIT(n)  asm volatile("cp.async.wait_group %0;" :: "n"(n) : "memory")

__device__ __forceinline__ void split_bf16(float v, __nv_bfloat16& h, __nv_bfloat16& l) {
    h = __float2bfloat16(v);
    l = __float2bfloat16(v - __bfloat162float(h));
}

// ======================= prep mega-kernel =======================
// grid (16,16,6), block (32,8)
//   z=0..3 : transpose+split weight z
//   z=4    : zero g_cnt and ssrc/sdst
//   z=5    : split input activations x -> Ah/Al
__global__ void k_prep(const float* __restrict__ x,
                       __nv_bfloat16* __restrict__ Ah, __nv_bfloat16* __restrict__ Al,
                       const float* __restrict__ W0, const float* __restrict__ W1,
                       const float* __restrict__ W2, const float* __restrict__ W3) {
    int z = blockIdx.z;
    int tx = threadIdx.x, ty = threadIdx.y;
    int tid = ty * 32 + tx;
    if (z < 4) {
        const float* W = (z == 0) ? W0 : (z == 1) ? W1 : (z == 2) ? W2 : W3;
        int Nn = (z == 3) ? CC : HC;
        int bx = blockIdx.x * 32;
        int by = blockIdx.y * 32;
        if (bx >= Nn) return;
        __shared__ float t[32][33];
#pragma unroll
        for (int j = 0; j < 32; j += 8)
            t[ty + j][tx] = W[(size_t)(by + ty + j) * Nn + bx + tx];
        __syncthreads();
        __nv_bfloat16* th = g_WthA[z];
        __nv_bfloat16* tl = g_WtlA[z];
#pragma unroll
        for (int j = 0; j < 32; j += 8) {
            float v = t[tx][ty + j];
            __nv_bfloat16 h, l;
            split_bf16(v, h, l);
            size_t o = (size_t)(bx + ty + j) * HC + by + tx;
            th[o] = h; tl[o] = l;
        }
    } else if (z == 4) {
        int i = (blockIdx.y * 16 + blockIdx.x) * 256 + tid;
        if (i < NN) g_cnt[i] = 0;
        for (int s = i; s < NN * HH; s += 65536) { g_ssrc[s] = 0.f; g_sdst[s] = 0.f; }
    } else {
        const int n4 = NN * HC / 4;
        int i = (blockIdx.y * 16 + blockIdx.x) * 256 + tid;
        for (; i < n4; i += 65536) {
            float4 v = ((const float4*)x)[i];
            __nv_bfloat16 h0, h1, h2, h3, l0, l1, l2, l3;
            split_bf16(v.x, h0, l0); split_bf16(v.y, h1, l1);
            split_bf16(v.z, h2, l2); split_bf16(v.w, h3, l3);
            ((__nv_bfloat162*)Ah)[2 * i]     = __halves2bfloat162(h0, h1);
            ((__nv_bfloat162*)Ah)[2 * i + 1] = __halves2bfloat162(h2, h3);
            ((__nv_bfloat162*)Al)[2 * i]     = __halves2bfloat162(l0, l1);
            ((__nv_bfloat162*)Al)[2 * i + 1] = __halves2bfloat162(l2, l3);
        }
    }
}

// ======================= cp.async double-buffered warp-MMA GEMM =======================
// Optionally fuses the attention score reduction into the epilogue:
// ssrc[n,head] += sum_c h[n,head,c]*aS[head,c]  (head == blockIdx.x since BN==CC==64)
#define AH_OFF 0
#define AL_OFF 16384
#define BH_OFF 32768
#define BL_OFF 40960
#define STG    49152
#define SMEM_GEMM (2 * STG)

__global__ __launch_bounds__(256, 2)
void k_gemm_mma(const __nv_bfloat16* __restrict__ Ah, const __nv_bfloat16* __restrict__ Al,
                const __nv_bfloat16* __restrict__ Bh, const __nv_bfloat16* __restrict__ Bl,
                const float* __restrict__ bias, float* __restrict__ Cm,
                __nv_bfloat16* __restrict__ outH, __nv_bfloat16* __restrict__ outL,
                const float* __restrict__ aS, const float* __restrict__ aD, int Hh,
                int M, int Nn) {
    extern __shared__ char smem[];
    const uint32_t sb = smem_to_u32(smem);
    const int tid = threadIdx.x;
    const int lane = tid & 31;
    const int wid = tid >> 5;
    const int warpM = wid & 3;
    const int warpN = wid >> 2;
    const int bm = blockIdx.y * 128;
    const int bn = blockIdx.x * 64;

    float acc[2][4][4];
#pragma unroll
    for (int mt = 0; mt < 2; mt++)
#pragma unroll
        for (int nt = 0; nt < 4; nt++)
#pragma unroll
            for (int r = 0; r < 4; r++) acc[mt][nt][r] = 0.f;

    auto issue = [&](int kb, int buf) {
        const uint32_t sbase = sb + buf * STG;
#pragma unroll
        for (int it = 0; it < 4; it++) {
            int idx = tid + it * 256;
            int r = idx >> 3, c16 = idx & 7;
            uint32_t so = (uint32_t)(r * 128 + c16 * 16);
            so ^= (so >> 3) & 0x70;
            int gr = bm + r;
            int grc = gr < M ? gr : 0;
            int sz = gr < M ? 16 : 0;
            size_t goff = (size_t)grc * 512 + kb * 64 + c16 * 8;
            cp16(sbase + AH_OFF + so, Ah + goff, sz);
            cp16(sbase + AL_OFF + so, Al + goff, sz);
        }
#pragma unroll
        for (int it = 0; it < 2; it++) {
            int idx = tid + it * 256;
            int r = idx >> 3, c16 = idx & 7;
            uint32_t so = (uint32_t)(r * 128 + c16 * 16);
            so ^= (so >> 3) & 0x70;
            size_t goff = (size_t)(bn + r) * 512 + kb * 64 + c16 * 8;
            cp16(sbase + BH_OFF + so, Bh + goff, 16);
            cp16(sbase + BL_OFF + so, Bl + goff, 16);
        }
    };

    const uint32_t aRow = (uint32_t)(warpM * 32 + (lane & 15));
    const uint32_t aC16b = (uint32_t)(lane >> 4);
    const uint32_t bRow = (uint32_t)(warpN * 32 + ((lane >> 4) << 3) + (lane & 7));
    const uint32_t bC16b = (uint32_t)((lane >> 3) & 1);

    issue(0, 0);
    CP_COMMIT();

    for (int kb = 0; kb < 8; kb++) {
        if (kb + 1 < 8) { issue(kb + 1, (kb + 1) & 1); CP_COMMIT(); }
        if (kb + 1 < 8) { CP_WAIT(1); } else { CP_WAIT(0); }
        __syncthreads();
        const uint32_t sbase = sb + (kb & 1) * STG;
#pragma unroll
        for (int ks = 0; ks < 4; ks++) {
            uint32_t ah[2][4], al[2][4], bh[2][4], bl[2][4];
            uint32_t ac16 = (uint32_t)(ks * 2) + aC16b;
#pragma unroll
            for (int mt = 0; mt < 2; mt++) {
                uint32_t off = (aRow + mt * 16) * 128 + ac16 * 16;
                off ^= (off >> 3) & 0x70;
                ldm_x4(ah[mt], sbase + AH_OFF + off);
                ldm_x4(al[mt], sbase + AL_OFF + off);
            }
            uint32_t bc16 = (uint32_t)(ks * 2) + bC16b;
#pragma unroll
            for (int half = 0; half < 2; half++) {
                uint32_t off = (bRow + half * 16) * 128 + bc16 * 16;
                off ^= (off >> 3) & 0x70;
                ldm_x4(bh[half], sbase + BH_OFF + off);
                ldm_x4(bl[half], sbase + BL_OFF + off);
            }
#pragma unroll
            for (int mt = 0; mt < 2; mt++) {
#pragma unroll
                for (int nt = 0; nt < 4; nt++) {
                    const uint32_t* bhf = &bh[nt >> 1][(nt & 1) * 2];
                    const uint32_t* blf = &bl[nt >> 1][(nt & 1) * 2];
                    mma16816(acc[mt][nt], ah[mt], bhf);
                    mma16816(acc[mt][nt], al[mt], bhf);
                    mma16816(acc[mt][nt], ah[mt], blf);
                }
            }
        }
        __syncthreads();
    }

    const int rowBase = bm + warpM * 32 + (lane >> 2);
    const int colBase = bn + warpN * 32 + (lane & 3) * 2;
#pragma unroll
    for (int mt = 0; mt < 2; mt++) {
#pragma unroll
        for (int nt = 0; nt < 4; nt++) {
            int gc = colBase + nt * 8;
            float b0 = 0.f, b1 = 0.f;
            if (bias) { b0 = bias[gc]; b1 = bias[gc + 1]; }
#pragma unroll
            for (int half = 0; half < 2; half++) {
                int r = rowBase + mt * 16 + half * 8;
                if (r < M) {
                    float v0 = acc[mt][nt][half * 2] + b0;
                    float v1 = acc[mt][nt][half * 2 + 1] + b1;
                    *(float2*)(Cm + (size_t)r * Nn + gc) = make_float2(v0, v1);
                    if (outH) {
                        __nv_bfloat16 h0, h1, l0, l1;
                        split_bf16(v0, h0, l0);
                        split_bf16(v1, h1, l1);
                        *(__nv_bfloat162*)(outH + (size_t)r * Nn + gc) = __halves2bfloat162(h0, h1);
                        *(__nv_bfloat162*)(outL + (size_t)r * Nn + gc) = __halves2bfloat162(l0, l1);
                    }
                }
            }
        }
    }

    // ---- fused attention score partials ----
    if (aS) {
        const int head = blockIdx.x;           // BN == CC == 64
        const float* aSh = aS + head * CC;
        const float* aDh = aD + head * CC;
        const int colh0 = warpN * 32 + (lane & 3) * 2;
#pragma unroll
        for (int mt = 0; mt < 2; mt++) {
#pragma unroll
            for (int half = 0; half < 2; half++) {
                float s1 = 0.f, s2 = 0.f;
#pragma unroll
                for (int nt = 0; nt < 4; nt++) {
                    int colh = colh0 + nt * 8;
                    float v0 = acc[mt][nt][half * 2];
                    float v1 = acc[mt][nt][half * 2 + 1];
                    s1 += v0 * aSh[colh] + v1 * aSh[colh + 1];
                    s2 += v0 * aDh[colh] + v1 * aDh[colh + 1];
                }
                s1 += __shfl_xor_sync(0xffffffffu, s1, 1);
                s1 += __shfl_xor_sync(0xffffffffu, s1, 2);
                s2 += __shfl_xor_sync(0xffffffffu, s2, 1);
                s2 += __shfl_xor_sync(0xffffffffu, s2, 2);
                int r = rowBase + mt * 16 + half * 8;
                if ((lane & 3) == 0 && r < M) {
                    atomicAdd(&g_ssrc[r * Hh + head], s1);
                    atomicAdd(&g_sdst[r * Hh + head], s2);
                }
            }
        }
    }
}

// ---------------- CSR build ----------------
__global__ void k_count(const int* __restrict__ ei) {
    int e = blockIdx.x * blockDim.x + threadIdx.x;
    if (e < EE) atomicAdd(&g_cnt[ei[EE + e]], 1);
}
__global__ void k_scan() {
    __shared__ int sh[1024];
    __shared__ int carry;
    int tid = threadIdx.x;
    if (tid == 0) carry = 0;
    __syncthreads();
    for (int base = 0; base < NN; base += 1024) {
        int i = base + tid;
        int v = (i < NN) ? (g_cnt[i] + 1) : 0;
        sh[tid] = v;
        __syncthreads();
        for (int off = 1; off < 1024; off <<= 1) {
            int t = (tid >= off) ? sh[tid - off] : 0;
            __syncthreads();
            sh[tid] += t;
            __syncthreads();
        }
        if (i < NN) g_rowptr[i + 1] = carry + sh[tid];
        __syncthreads();
        if (tid == 1023) carry += sh[1023];
        __syncthreads();
    }
    if (tid == 0) g_rowptr[0] = 0;
}
__global__ void k_fill_self() {
    int i = blockIdx.x * blockDim.x + threadIdx.x;
    if (i < NN) {
        int rp = g_rowptr[i];
        g_csrc[rp] = i;
        g_cnt[i] = rp + 1;
    }
}
__global__ void k_fill(const int* __restrict__ ei) {
    int e = blockIdx.x * blockDim.x + threadIdx.x;
    if (e < EE) {
        int dst = ei[EE + e];
        int slot = atomicAdd(&g_cnt[dst], 1);
        g_csrc[slot] = ei[e];
    }
}

__device__ __forceinline__ float lrelu02(float x) { return x > 0.f ? x : 0.2f * x; }

// ---------------- GAT aggregation, H=8, shared-alpha ----------------
__global__ void k_agg8(const float* __restrict__ hbuf, const float* __restrict__ ssrc,
                       const float* __restrict__ sdst, const float* __restrict__ bias,
                       float* __restrict__ out) {
    int dstn = blockIdx.x;
    int tid = threadIdx.x;
    __shared__ float sh_sdst[HH], sh_m[HH], sh_sinv[HH];
    __shared__ float sh_alpha[32 * HH];
    __shared__ int   sh_src[32];
    if (tid < HH) sh_sdst[tid] = sdst[dstn * HH + tid];
    __syncthreads();
    int beg = g_rowptr[dstn], end = g_rowptr[dstn + 1];
    int warp = tid >> 5, lane = tid & 31;
    {
        int hh = warp * 2 + (lane >> 4);
        int sub = lane & 15;
        float sd = sh_sdst[hh];
        float mx = -3.4e38f;
        for (int i = beg + sub; i < end; i += 16)
            mx = fmaxf(mx, lrelu02(ssrc[g_csrc[i] * HH + hh] + sd));
#pragma unroll
        for (int o = 1; o < 16; o <<= 1) mx = fmaxf(mx, __shfl_xor_sync(0xffffffffu, mx, o));
        float se = 0.f;
        for (int i = beg + sub; i < end; i += 16)
            se += __expf(lrelu02(ssrc[g_csrc[i] * HH + hh] + sd) - mx);
#pragma unroll
        for (int o = 1; o < 16; o <<= 1) se += __shfl_xor_sync(0xffffffffu, se, o);
        if (sub == 0) { sh_m[hh] = mx; sh_sinv[hh] = 1.f / (se + 1e-16f); }
    }
    __syncthreads();
    int hh = tid >> 4;
    int c4 = (tid & 15) << 2;
    float4 acc = make_float4(0.f, 0.f, 0.f, 0.f);
    for (int c0 = beg; c0 < end; c0 += 32) {
        int cnt = min(32, end - c0);
        for (int t = tid; t < cnt * HH; t += 128) {
            int e = t >> 3, h2 = t & 7;
            int s = g_csrc[c0 + e];
            if (h2 == 0) sh_src[e] = s;
            sh_alpha[e * HH + h2] =
                __expf(lrelu02(ssrc[s * HH + h2] + sh_sdst[h2]) - sh_m[h2]) * sh_sinv[h2];
        }
        __syncthreads();
        int e = 0;
        for (; e + 1 < cnt; e += 2) {
            float a0 = sh_alpha[e * HH + hh];
            float a1 = sh_alpha[(e + 1) * HH + hh];
            float4 v0 = *(const float4*)(hbuf + (size_t)sh_src[e] * HC + hh * CC + c4);
            float4 v1 = *(const float4*)(hbuf + (size_t)sh_src[e + 1] * HC + hh * CC + c4);
            acc.x = fmaf(a0, v0.x, fmaf(a1, v1.x, acc.x));
            acc.y = fmaf(a0, v0.y, fmaf(a1, v1.y, acc.y));
            acc.z = fmaf(a0, v0.z, fmaf(a1, v1.z, acc.z));
            acc.w = fmaf(a0, v0.w, fmaf(a1, v1.w, acc.w));
        }
        if (e < cnt) {
            float a0 = sh_alpha[e * HH + hh];
            float4 v0 = *(const float4*)(hbuf + (size_t)sh_src[e] * HC + hh * CC + c4);
            acc.x = fmaf(a0, v0.x, acc.x);
            acc.y = fmaf(a0, v0.y, acc.y);
            acc.z = fmaf(a0, v0.z, acc.z);
            acc.w = fmaf(a0, v0.w, acc.w);
        }
        __syncthreads();
    }
    float4 bb = *(const float4*)(bias + hh * CC + c4);
    acc.x += bb.x; acc.y += bb.y; acc.z += bb.z; acc.w += bb.w;
    *(float4*)(out + (size_t)dstn * HC + hh * CC + c4) = acc;
}

// ---------------- GAT aggregation, H=1 C=64, shared-alpha ----------------
__global__ void k_agg1(const float* __restrict__ h3, const float* __restrict__ ssrc,
                       const float* __restrict__ sdst, const float* __restrict__ bias,
                       float* __restrict__ out) {
    int dstn = blockIdx.x;
    int tid = threadIdx.x;
    __shared__ float sh_m, sh_sinv;
    __shared__ float sh_alpha[64];
    __shared__ int   sh_src[64];
    float sd = sdst[dstn];
    int beg = g_rowptr[dstn], end = g_rowptr[dstn + 1];
    if (tid < 32) {
        float mx = -3.4e38f;
        for (int i = beg + tid; i < end; i += 32)
            mx = fmaxf(mx, lrelu02(ssrc[g_csrc[i]] + sd));
#pragma unroll
        for (int o = 1; o < 32; o <<= 1) mx = fmaxf(mx, __shfl_xor_sync(0xffffffffu, mx, o));
        float se = 0.f;
        for (int i = beg + tid; i < end; i += 32)
            se += __expf(lrelu02(ssrc[g_csrc[i]] + sd) - mx);
#pragma unroll
        for (int o = 1; o < 32; o <<= 1) se += __shfl_xor_sync(0xffffffffu, se, o);
        if (tid == 0) { sh_m = mx; sh_sinv = 1.f / (se + 1e-16f); }
    }
    __syncthreads();
    float m = sh_m, sinv = sh_sinv;
    float acc = 0.f;
    for (int c0 = beg; c0 < end; c0 += 64) {
        int cnt = min(64, end - c0);
        if (tid < cnt) {
            int s = g_csrc[c0 + tid];
            sh_src[tid] = s;
            sh_alpha[tid] = __expf(lrelu02(ssrc[s] + sd) - m) * sinv;
        }
        __syncthreads();
        int e = 0;
        for (; e + 1 < cnt; e += 2) {
            float a0 = sh_alpha[e], a1 = sh_alpha[e + 1];
            float v0 = h3[(size_t)sh_src[e] * CC + tid];
            float v1 = h3[(size_t)sh_src[e + 1] * CC + tid];
            acc = fmaf(a0, v0, fmaf(a1, v1, acc));
        }
        if (e < cnt)
            acc = fmaf(sh_alpha[e], h3[(size_t)sh_src[e] * CC + tid], acc);
        __syncthreads();
    }
    out[(size_t)dstn * CC + tid] = acc + bias[tid];
}

// ---------------- BatchNorm (training stats) ----------------
__global__ void k_bnstats(const float* __restrict__ x, int Cdim, int rowsPerBlock) {
    int c = threadIdx.x;
    int b = blockIdx.x;
    int r0 = b * rowsPerBlock;
    int r1 = min(r0 + rowsPerBlock, NN);
    float s = 0.f, q = 0.f;
    for (int r = r0; r < r1; r++) {
        float v = x[(size_t)r * Cdim + c];
        s += v; q = fmaf(v, v, q);
    }
    g_bnpart[b * Cdim + c] = s;
    g_bnpart2[b * Cdim + c] = q;
}

__global__ void k_bnfinal(const float* __restrict__ g, const float* __restrict__ be, int Cdim) {
    int c = threadIdx.x;
    if (c >= Cdim) return;
    float s = 0.f, q = 0.f;
    for (int b = 0; b < NBN; b++) {
        s += g_bnpart[b * Cdim + c];
        q += g_bnpart2[b * Cdim + c];
    }
    float mu = s / (float)NN;
    float var = q / (float)NN - mu * mu;
    var = fmaxf(var, 0.f);
    float inv = rsqrtf(var + 1e-5f);
    float sc = g[c] * inv;
    g_scale[c] = sc;
    g_shift[c] = be[c] - sc * mu;
}

// out = res + elu(scale*in+shift); optional bf16 split; optional score-buffer zeroing
__global__ void k_bnapply(const float* __restrict__ in, const float* __restrict__ res,
                          float* __restrict__ out,
                          __nv_bfloat16* __restrict__ outH, __nv_bfloat16* __restrict__ outL,
                          int Cdim, int doElu, int total4, int zeroScores) {
    int i0 = blockIdx.x * blockDim.x + threadIdx.x;
    int stride = gridDim.x * blockDim.x;
    if (zeroScores) {
        for (int zi = i0; zi < NN * HH; zi += stride) { g_ssrc[zi] = 0.f; g_sdst[zi] = 0.f; }
    }
    int c4cnt = Cdim >> 2;
    for (int i = i0; i < total4; i += stride) {
        int c4 = (i % c4cnt) << 2;
        float4 v = ((const float4*)in)[i];
        float4 sc = *(const float4*)&g_scale[c4];
        float4 sh = *(const float4*)&g_shift[c4];
        float o0 = fmaf(sc.x, v.x, sh.x);
        float o1 = fmaf(sc.y, v.y, sh.y);
        float o2 = fmaf(sc.z, v.z, sh.z);
        float o3 = fmaf(sc.w, v.w, sh.w);
        if (doElu) {
            o0 = o0 > 0.f ? o0 : expm1f(o0);
            o1 = o1 > 0.f ? o1 : expm1f(o1);
            o2 = o2 > 0.f ? o2 : expm1f(o2);
            o3 = o3 > 0.f ? o3 : expm1f(o3);
        }
        if (res) {
            float4 rv = ((const float4*)res)[i];
            o0 += rv.x; o1 += rv.y; o2 += rv.z; o3 += rv.w;
        }
        ((float4*)out)[i] = make_float4(o0, o1, o2, o3);
        if (outH) {
            __nv_bfloat16 h0, h1, h2, h3, l0, l1, l2, l3;
            split_bf16(o0, h0, l0); split_bf16(o1, h1, l1);
            split_bf16(o2, h2, l2); split_bf16(o3, h3, l3);
            ((__nv_bfloat162*)outH)[2 * i]     = __halves2bfloat162(h0, h1);
            ((__nv_bfloat162*)outH)[2 * i + 1] = __halves2bfloat162(h2, h3);
            ((__nv_bfloat162*)outL)[2 * i]     = __halves2bfloat162(l0, l1);
            ((__nv_bfloat162*)outL)[2 * i + 1] = __halves2bfloat162(l2, l3);
        }
    }
}

// ---------------- fused pool + classifier (batch is sorted) ----------------
__global__ void k_poolfinal(const float* __restrict__ x3, const int* __restrict__ batch,
                            const float* __restrict__ linW, const float* __restrict__ linb,
                            float* __restrict__ out) {
    int g = blockIdx.x;
    int j = threadIdx.x;
    __shared__ float xg[CC];
    int lo = 0, hi = NN;
    while (lo < hi) { int mid = (lo + hi) >> 1; if (batch[mid] < g) lo = mid + 1; else hi = mid; }
    int beg = lo;
    hi = NN;
    while (lo < hi) { int mid = (lo + hi) >> 1; if (batch[mid] <= g) lo = mid + 1; else hi = mid; }
    int end = lo;
    float s = 0.f;
    for (int n = beg; n < end; n++) s += x3[(size_t)n * CC + j];
    float cv = fmaxf((float)(end - beg), 1.0f);
    xg[j] = s / cv;
    __syncthreads();
    float acc = linb[j];
#pragma unroll
    for (int c = 0; c < CC; c++) acc = fmaf(xg[c], linW[c * NCLS + j], acc);
    out[g * NCLS + j] = acc;
}

// ---------------- host side ----------------
extern "C" void kernel_launch(void* const* d_in, const int* in_sizes, int n_in,
                              void* d_out, int out_size) {
    const float* x      = (const float*)d_in[0];
    const int*   ei     = (const int*)d_in[1];
    const int*   batch  = (const int*)d_in[2];
    const float* enc_W  = (const float*)d_in[3];
    const float* enc_b  = (const float*)d_in[4];
    const float* W1     = (const float*)d_in[5];
    const float* as1    = (const float*)d_in[6];
    const float* ad1    = (const float*)d_in[7];
    const float* b1     = (const float*)d_in[8];
    const float* g1     = (const float*)d_in[9];
    const float* be1    = (const float*)d_in[10];
    const float* W2     = (const float*)d_in[11];
    const float* as2    = (const float*)d_in[12];
    const float* ad2    = (const float*)d_in[13];
    const float* b2     = (const float*)d_in[14];
    const float* g2     = (const float*)d_in[15];
    const float* be2    = (const float*)d_in[16];
    const float* W3     = (const float*)d_in[17];
    const float* as3    = (const float*)d_in[18];
    const float* ad3    = (const float*)d_in[19];
    const float* b3     = (const float*)d_in[20];
    const float* g3     = (const float*)d_in[21];
    const float* be3    = (const float*)d_in[22];
    const float* linW   = (const float*)d_in[23];
    const float* linb   = (const float*)d_in[24];
    float* out = (float*)d_out;

    float *bufA, *bufB, *hbuf, *gat, *ssrc, *sdst, *x3, *gat3;
    __nv_bfloat16 *Ah, *Al, *Ah2, *Al2, *Wth, *Wtl;
    cudaGetSymbolAddress((void**)&bufA, g_bufA);
    cudaGetSymbolAddress((void**)&bufB, g_bufB);
    cudaGetSymbolAddress((void**)&hbuf, g_h);
    cudaGetSymbolAddress((void**)&gat,  g_gat);
    cudaGetSymbolAddress((void**)&ssrc, g_ssrc);
    cudaGetSymbolAddress((void**)&sdst, g_sdst);
    cudaGetSymbolAddress((void**)&x3,   g_x3);
    cudaGetSymbolAddress((void**)&gat3, g_gat3);
    cudaGetSymbolAddress((void**)&Ah,   g_Ah);
    cudaGetSymbolAddress((void**)&Al,   g_Al);
    cudaGetSymbolAddress((void**)&Ah2,  g_Ah2);
    cudaGetSymbolAddress((void**)&Al2,  g_Al2);
    cudaGetSymbolAddress((void**)&Wth,  g_WthA);
    cudaGetSymbolAddress((void**)&Wtl,  g_WtlA);
    __nv_bfloat16 *Wth0 = Wth,              *Wtl0 = Wtl;
    __nv_bfloat16 *Wth1 = Wth + HC * HC,    *Wtl1 = Wtl + HC * HC;
    __nv_bfloat16 *Wth2 = Wth + 2 * HC * HC,*Wtl2 = Wtl + 2 * HC * HC;
    __nv_bfloat16 *Wth3 = Wth + 3 * HC * HC,*Wtl3 = Wtl + 3 * HC * HC;

    cudaFuncSetAttribute(k_gemm_mma, cudaFuncAttributeMaxDynamicSharedMemorySize, SMEM_GEMM);

    dim3 gGrid(HC / 64, (NN + 127) / 128);
    dim3 gGrid3(1, (NN + 127) / 128);
    const int T4 = NN * HC / 4;
    const int T4c = NN * CC / 4;

    // launch 0: prep (weights + input split + zero cnt/scores)
    k_prep<<<dim3(16, 16, 6), dim3(32, 8)>>>(x, Ah, Al, enc_W, W1, W2, W3);
    // launches 1-2: CSR count + scan
    k_count<<<(EE + 255) / 256, 256>>>(ei);
    k_scan<<<1, 1024>>>();
    // launch 3 (ncu-profiled slot): encoder GEMM
    k_gemm_mma<<<gGrid, 256, SMEM_GEMM>>>(Ah, Al, Wth0, Wtl0, enc_b, bufA, Ah2, Al2,
                                          nullptr, nullptr, HH, NN, HC);
    // launches 4-5: CSR fill
    k_fill_self<<<(NN + 255) / 256, 256>>>();
    k_fill<<<(EE + 255) / 256, 256>>>(ei);

    // ---- layer 1 (GEMM computes scores into ssrc/sdst) ----
    k_gemm_mma<<<gGrid, 256, SMEM_GEMM>>>(Ah2, Al2, Wth1, Wtl1, nullptr, hbuf, nullptr, nullptr,
                                          as1, ad1, HH, NN, HC);
    k_agg8<<<NN, 128>>>(hbuf, ssrc, sdst, b1, gat);
    k_bnstats<<<NBN, HC>>>(gat, HC, NN / NBN);
    k_bnfinal<<<1, HC>>>(g1, be1, HC);
    k_bnapply<<<512, 256>>>(gat, bufA, bufB, Ah, Al, HC, 1, T4, 1);

    // ---- layer 2 ----
    k_gemm_mma<<<gGrid, 256, SMEM_GEMM>>>(Ah, Al, Wth2, Wtl2, nullptr, hbuf, nullptr, nullptr,
                                          as2, ad2, HH, NN, HC);
    k_agg8<<<NN, 128>>>(hbuf, ssrc, sdst, b2, gat);
    k_bnstats<<<NBN, HC>>>(gat, HC, NN / NBN);
    k_bnfinal<<<1, HC>>>(g2, be2, HC);
    k_bnapply<<<512, 256>>>(gat, bufB, bufA, Ah2, Al2, HC, 1, T4, 1);

    // ---- layer 3 (H=1) ----
    k_gemm_mma<<<gGrid3, 256, SMEM_GEMM>>>(Ah2, Al2, Wth3, Wtl3, nullptr, x3, nullptr, nullptr,
                                           as3, ad3, 1, NN, CC);
    k_agg1<<<NN, 64>>>(x3, ssrc, sdst, b3, gat3);
    k_bnstats<<<NBN, CC>>>(gat3, CC, NN / NBN);
    k_bnfinal<<<1, CC>>>(g3, be3, CC);
    k_bnapply<<<256, 256>>>(gat3, nullptr, x3, nullptr, nullptr, CC, 0, T4c, 0);

    // ---- fused pool + classifier ----
    k_poolfinal<<<GG, NCLS>>>(x3, batch, linW, linb, out);
}

// round 11
// speedup vs baseline: 2.1655x; 1.0133x over previous
#include <cuda_runtime.h>
#include <cuda_bf16.h>
#include <math.h>
#include <stdint.h>

// Problem constants
#define NN    10000
#define EE    160000
#define EP    170000
#define HH    8
#define CC    64
#define HC    512
#define GG    64
#define NCLS  64
#define NBN   100            // bn partial blocks

// ---------------- device scratch ----------------
__device__ float g_bufA[NN * HC];
__device__ float g_bufB[NN * HC];
__device__ float g_h[NN * HC];
__device__ float g_gat[NN * HC];
__device__ float g_ssrc[NN * HH];
__device__ float g_sdst[NN * HH];
__device__ float g_x3[NN * CC];
__device__ float g_gat3[NN * CC];
__device__ int   g_rowptr[NN + 1];
__device__ int   g_cnt[NN];
__device__ int   g_csrc[EP];
__device__ float g_bnpart[NBN * HC];
__device__ float g_bnpart2[NBN * HC];
__device__ int   g_bncnt;
__device__ float g_scale[HC];
__device__ float g_shift[HC];
__device__ __nv_bfloat16 g_Ah[NN * HC];
__device__ __nv_bfloat16 g_Al[NN * HC];
__device__ __nv_bfloat16 g_Ah2[NN * HC];
__device__ __nv_bfloat16 g_Al2[NN * HC];
__device__ __nv_bfloat16 g_WthA[4][HC * HC];
__device__ __nv_bfloat16 g_WtlA[4][HC * HC];

// ======================= helpers =======================
__device__ __forceinline__ uint32_t smem_to_u32(const void* p) {
    uint32_t a;
    asm("{ .reg .u64 t; cvta.to.shared.u64 t, %1; cvt.u32.u64 %0, t; }" : "=r"(a) : "l"(p));
    return a;
}
__device__ __forceinline__ void ldm_x4(uint32_t* r, uint32_t addr) {
    asm volatile("ldmatrix.sync.aligned.m8n8.x4.shared.b16 {%0,%1,%2,%3}, [%4];"
                 : "=r"(r[0]), "=r"(r[1]), "=r"(r[2]), "=r"(r[3]) : "r"(addr));
}
__device__ __forceinline__ void mma16816(float* c, const uint32_t* a, const uint32_t* b) {
    asm volatile(
        "mma.sync.aligned.m16n8k16.row.col.f32.bf16.bf16.f32 "
        "{%0,%1,%2,%3}, {%4,%5,%6,%7}, {%8,%9}, {%0,%1,%2,%3};"
        : "+f"(c[0]), "+f"(c[1]), "+f"(c[2]), "+f"(c[3])
        : "r"(a[0]), "r"(a[1]), "r"(a[2]), "r"(a[3]), "r"(b[0]), "r"(b[1]));
}
__device__ __forceinline__ void cp16(uint32_t dst, const void* src, int sz) {
    asm volatile("cp.async.cg.shared.global [%0], [%1], 16, %2;"
                 :: "r"(dst), "l"(src), "r"(sz));
}
#define CP_COMMIT() asm volatile("cp.async.commit_group;" ::: "memory")
#define CP_WAIT(n)  asm volatile("cp.async.wait_group %0;" :: "n"(n) : "memory")

__device__ __forceinline__ void split_bf16(float v, __nv_bfloat16& h, __nv_bfloat16& l) {
    h = __float2bfloat16(v);
    l = __float2bfloat16(v - __bfloat162float(h));
}

// ======================= prep mega-kernel =======================
__global__ void k_prep(const float* __restrict__ x,
                       __nv_bfloat16* __restrict__ Ah, __nv_bfloat16* __restrict__ Al,
                       const float* __restrict__ W0, const float* __restrict__ W1,
                       const float* __restrict__ W2, const float* __restrict__ W3) {
    int z = blockIdx.z;
    int tx = threadIdx.x, ty = threadIdx.y;
    int tid = ty * 32 + tx;
    if (z < 4) {
        const float* W = (z == 0) ? W0 : (z == 1) ? W1 : (z == 2) ? W2 : W3;
        int Nn = (z == 3) ? CC : HC;
        int bx = blockIdx.x * 32;
        int by = blockIdx.y * 32;
        if (bx >= Nn) return;
        __shared__ float t[32][33];
#pragma unroll
        for (int j = 0; j < 32; j += 8)
            t[ty + j][tx] = W[(size_t)(by + ty + j) * Nn + bx + tx];
        __syncthreads();
        __nv_bfloat16* th = g_WthA[z];
        __nv_bfloat16* tl = g_WtlA[z];
#pragma unroll
        for (int j = 0; j < 32; j += 8) {
            float v = t[tx][ty + j];
            __nv_bfloat16 h, l;
            split_bf16(v, h, l);
            size_t o = (size_t)(bx + ty + j) * HC + by + tx;
            th[o] = h; tl[o] = l;
        }
    } else if (z == 4) {
        int i = (blockIdx.y * 16 + blockIdx.x) * 256 + tid;
        if (i == 0) g_bncnt = 0;
        if (i < NN) g_cnt[i] = 0;
        for (int s = i; s < NN * HH; s += 65536) { g_ssrc[s] = 0.f; g_sdst[s] = 0.f; }
    } else {
        const int n4 = NN * HC / 4;
        int i = (blockIdx.y * 16 + blockIdx.x) * 256 + tid;
        for (; i < n4; i += 65536) {
            float4 v = ((const float4*)x)[i];
            __nv_bfloat16 h0, h1, h2, h3, l0, l1, l2, l3;
            split_bf16(v.x, h0, l0); split_bf16(v.y, h1, l1);
            split_bf16(v.z, h2, l2); split_bf16(v.w, h3, l3);
            ((__nv_bfloat162*)Ah)[2 * i]     = __halves2bfloat162(h0, h1);
            ((__nv_bfloat162*)Ah)[2 * i + 1] = __halves2bfloat162(h2, h3);
            ((__nv_bfloat162*)Al)[2 * i]     = __halves2bfloat162(l0, l1);
            ((__nv_bfloat162*)Al)[2 * i + 1] = __halves2bfloat162(l2, l3);
        }
    }
}

// ======================= cp.async double-buffered warp-MMA GEMM =======================
// Pass-major MMA order: hh-pass MMAs overlap the al/bl ldmatrix latency.
#define AH_OFF 0
#define AL_OFF 16384
#define BH_OFF 32768
#define BL_OFF 40960
#define STG    49152
#define SMEM_GEMM (2 * STG)

__global__ __launch_bounds__(256, 2)
void k_gemm_mma(const __nv_bfloat16* __restrict__ Ah, const __nv_bfloat16* __restrict__ Al,
                const __nv_bfloat16* __restrict__ Bh, const __nv_bfloat16* __restrict__ Bl,
                const float* __restrict__ bias, float* __restrict__ Cm,
                __nv_bfloat16* __restrict__ outH, __nv_bfloat16* __restrict__ outL,
                const float* __restrict__ aS, const float* __restrict__ aD, int Hh,
                int M, int Nn) {
    extern __shared__ char smem[];
    const uint32_t sb = smem_to_u32(smem);
    const int tid = threadIdx.x;
    const int lane = tid & 31;
    const int wid = tid >> 5;
    const int warpM = wid & 3;
    const int warpN = wid >> 2;
    const int bm = blockIdx.y * 128;
    const int bn = blockIdx.x * 64;

    float acc[2][4][4];
#pragma unroll
    for (int mt = 0; mt < 2; mt++)
#pragma unroll
        for (int nt = 0; nt < 4; nt++)
#pragma unroll
            for (int r = 0; r < 4; r++) acc[mt][nt][r] = 0.f;

    auto issue = [&](int kb, int buf) {
        const uint32_t sbase = sb + buf * STG;
#pragma unroll
        for (int it = 0; it < 4; it++) {
            int idx = tid + it * 256;
            int r = idx >> 3, c16 = idx & 7;
            uint32_t so = (uint32_t)(r * 128 + c16 * 16);
            so ^= (so >> 3) & 0x70;
            int gr = bm + r;
            int grc = gr < M ? gr : 0;
            int sz = gr < M ? 16 : 0;
            size_t goff = (size_t)grc * 512 + kb * 64 + c16 * 8;
            cp16(sbase + AH_OFF + so, Ah + goff, sz);
            cp16(sbase + AL_OFF + so, Al + goff, sz);
        }
#pragma unroll
        for (int it = 0; it < 2; it++) {
            int idx = tid + it * 256;
            int r = idx >> 3, c16 = idx & 7;
            uint32_t so = (uint32_t)(r * 128 + c16 * 16);
            so ^= (so >> 3) & 0x70;
            size_t goff = (size_t)(bn + r) * 512 + kb * 64 + c16 * 8;
            cp16(sbase + BH_OFF + so, Bh + goff, 16);
            cp16(sbase + BL_OFF + so, Bl + goff, 16);
        }
    };

    const uint32_t aRow = (uint32_t)(warpM * 32 + (lane & 15));
    const uint32_t aC16b = (uint32_t)(lane >> 4);
    const uint32_t bRow = (uint32_t)(warpN * 32 + ((lane >> 4) << 3) + (lane & 7));
    const uint32_t bC16b = (uint32_t)((lane >> 3) & 1);

    issue(0, 0);
    CP_COMMIT();

    for (int kb = 0; kb < 8; kb++) {
        if (kb + 1 < 8) { issue(kb + 1, (kb + 1) & 1); CP_COMMIT(); }
        if (kb + 1 < 8) { CP_WAIT(1); } else { CP_WAIT(0); }
        __syncthreads();
        const uint32_t sbase = sb + (kb & 1) * STG;
#pragma unroll
        for (int ks = 0; ks < 4; ks++) {
            uint32_t ah[2][4], al[2][4], bh[2][4], bl[2][4];
            uint32_t ac16 = (uint32_t)(ks * 2) + aC16b;
            uint32_t bc16 = (uint32_t)(ks * 2) + bC16b;
            // hi fragments first (first-needed)
#pragma unroll
            for (int mt = 0; mt < 2; mt++) {
                uint32_t off = (aRow + mt * 16) * 128 + ac16 * 16;
                off ^= (off >> 3) & 0x70;
                ldm_x4(ah[mt], sbase + AH_OFF + off);
            }
#pragma unroll
            for (int half = 0; half < 2; half++) {
                uint32_t off = (bRow + half * 16) * 128 + bc16 * 16;
                off ^= (off >> 3) & 0x70;
                ldm_x4(bh[half], sbase + BH_OFF + off);
            }
            // lo fragments issued now; latency hidden behind hh-pass MMAs
#pragma unroll
            for (int mt = 0; mt < 2; mt++) {
                uint32_t off = (aRow + mt * 16) * 128 + ac16 * 16;
                off ^= (off >> 3) & 0x70;
                ldm_x4(al[mt], sbase + AL_OFF + off);
            }
#pragma unroll
            for (int half = 0; half < 2; half++) {
                uint32_t off = (bRow + half * 16) * 128 + bc16 * 16;
                off ^= (off >> 3) & 0x70;
                ldm_x4(bl[half], sbase + BL_OFF + off);
            }
            // pass-major MMAs: hh, then lh, then hl
#pragma unroll
            for (int mt = 0; mt < 2; mt++)
#pragma unroll
                for (int nt = 0; nt < 4; nt++)
                    mma16816(acc[mt][nt], ah[mt], &bh[nt >> 1][(nt & 1) * 2]);
#pragma unroll
            for (int mt = 0; mt < 2; mt++)
#pragma unroll
                for (int nt = 0; nt < 4; nt++)
                    mma16816(acc[mt][nt], al[mt], &bh[nt >> 1][(nt & 1) * 2]);
#pragma unroll
            for (int mt = 0; mt < 2; mt++)
#pragma unroll
                for (int nt = 0; nt < 4; nt++)
                    mma16816(acc[mt][nt], ah[mt], &bl[nt >> 1][(nt & 1) * 2]);
        }
        __syncthreads();
    }

    const int rowBase = bm + warpM * 32 + (lane >> 2);
    const int colBase = bn + warpN * 32 + (lane & 3) * 2;
#pragma unroll
    for (int mt = 0; mt < 2; mt++) {
#pragma unroll
        for (int nt = 0; nt < 4; nt++) {
            int gc = colBase + nt * 8;
            float b0 = 0.f, b1 = 0.f;
            if (bias) { b0 = bias[gc]; b1 = bias[gc + 1]; }
#pragma unroll
            for (int half = 0; half < 2; half++) {
                int r = rowBase + mt * 16 + half * 8;
                if (r < M) {
                    float v0 = acc[mt][nt][half * 2] + b0;
                    float v1 = acc[mt][nt][half * 2 + 1] + b1;
                    *(float2*)(Cm + (size_t)r * Nn + gc) = make_float2(v0, v1);
                    if (outH) {
                        __nv_bfloat16 h0, h1, l0, l1;
                        split_bf16(v0, h0, l0);
                        split_bf16(v1, h1, l1);
                        *(__nv_bfloat162*)(outH + (size_t)r * Nn + gc) = __halves2bfloat162(h0, h1);
                        *(__nv_bfloat162*)(outL + (size_t)r * Nn + gc) = __halves2bfloat162(l0, l1);
                    }
                }
            }
        }
    }

    // ---- fused attention score partials ----
    if (aS) {
        const int head = blockIdx.x;           // BN == CC == 64
        const float* aSh = aS + head * CC;
        const float* aDh = aD + head * CC;
        const int colh0 = warpN * 32 + (lane & 3) * 2;
#pragma unroll
        for (int mt = 0; mt < 2; mt++) {
#pragma unroll
            for (int half = 0; half < 2; half++) {
                float s1 = 0.f, s2 = 0.f;
#pragma unroll
                for (int nt = 0; nt < 4; nt++) {
                    int colh = colh0 + nt * 8;
                    float v0 = acc[mt][nt][half * 2];
                    float v1 = acc[mt][nt][half * 2 + 1];
                    s1 += v0 * aSh[colh] + v1 * aSh[colh + 1];
                    s2 += v0 * aDh[colh] + v1 * aDh[colh + 1];
                }
                s1 += __shfl_xor_sync(0xffffffffu, s1, 1);
                s1 += __shfl_xor_sync(0xffffffffu, s1, 2);
                s2 += __shfl_xor_sync(0xffffffffu, s2, 1);
                s2 += __shfl_xor_sync(0xffffffffu, s2, 2);
                int r = rowBase + mt * 16 + half * 8;
                if ((lane & 3) == 0 && r < M) {
                    atomicAdd(&g_ssrc[r * Hh + head], s1);
                    atomicAdd(&g_sdst[r * Hh + head], s2);
                }
            }
        }
    }
}

// ---------------- CSR build ----------------
__global__ void k_count(const int* __restrict__ ei) {
    int e = blockIdx.x * blockDim.x + threadIdx.x;
    if (e < EE) atomicAdd(&g_cnt[ei[EE + e]], 1);
}
// scan + self-loop fill fused (single block)
__global__ void k_scanfill() {
    __shared__ int sh[1024];
    __shared__ int carry;
    int tid = threadIdx.x;
    if (tid == 0) carry = 0;
    __syncthreads();
    for (int base = 0; base < NN; base += 1024) {
        int i = base + tid;
        int v = (i < NN) ? (g_cnt[i] + 1) : 0;
        sh[tid] = v;
        __syncthreads();
        for (int off = 1; off < 1024; off <<= 1) {
            int t = (tid >= off) ? sh[tid - off] : 0;
            __syncthreads();
            sh[tid] += t;
            __syncthreads();
        }
        if (i < NN) g_rowptr[i + 1] = carry + sh[tid];
        __syncthreads();
        if (tid == 1023) carry += sh[1023];
        __syncthreads();
    }
    if (tid == 0) g_rowptr[0] = 0;
    __syncthreads();
    for (int i = tid; i < NN; i += 1024) {
        int rp = (i == 0) ? 0 : g_rowptr[i];
        g_csrc[rp] = i;
        g_cnt[i] = rp + 1;
    }
}
__global__ void k_fill(const int* __restrict__ ei) {
    int e = blockIdx.x * blockDim.x + threadIdx.x;
    if (e < EE) {
        int dst = ei[EE + e];
        int slot = atomicAdd(&g_cnt[dst], 1);
        g_csrc[slot] = ei[e];
    }
}

__device__ __forceinline__ float lrelu02(float x) { return x > 0.f ? x : 0.2f * x; }

// ---------------- GAT aggregation, H=8, shared-alpha ----------------
__global__ void k_agg8(const float* __restrict__ hbuf, const float* __restrict__ ssrc,
                       const float* __restrict__ sdst, const float* __restrict__ bias,
                       float* __restrict__ out) {
    int dstn = blockIdx.x;
    int tid = threadIdx.x;
    __shared__ float sh_sdst[HH], sh_m[HH], sh_sinv[HH];
    __shared__ float sh_alpha[32 * HH];
    __shared__ int   sh_src[32];
    if (tid < HH) sh_sdst[tid] = sdst[dstn * HH + tid];
    __syncthreads();
    int beg = g_rowptr[dstn], end = g_rowptr[dstn + 1];
    int warp = tid >> 5, lane = tid & 31;
    {
        int hh = warp * 2 + (lane >> 4);
        int sub = lane & 15;
        float sd = sh_sdst[hh];
        float mx = -3.4e38f;
        for (int i = beg + sub; i < end; i += 16)
            mx = fmaxf(mx, lrelu02(ssrc[g_csrc[i] * HH + hh] + sd));
#pragma unroll
        for (int o = 1; o < 16; o <<= 1) mx = fmaxf(mx, __shfl_xor_sync(0xffffffffu, mx, o));
        float se = 0.f;
        for (int i = beg + sub; i < end; i += 16)
            se += __expf(lrelu02(ssrc[g_csrc[i] * HH + hh] + sd) - mx);
#pragma unroll
        for (int o = 1; o < 16; o <<= 1) se += __shfl_xor_sync(0xffffffffu, se, o);
        if (sub == 0) { sh_m[hh] = mx; sh_sinv[hh] = 1.f / (se + 1e-16f); }
    }
    __syncthreads();
    int hh = tid >> 4;
    int c4 = (tid & 15) << 2;
    float4 acc = make_float4(0.f, 0.f, 0.f, 0.f);
    for (int c0 = beg; c0 < end; c0 += 32) {
        int cnt = min(32, end - c0);
        for (int t = tid; t < cnt * HH; t += 128) {
            int e = t >> 3, h2 = t & 7;
            int s = g_csrc[c0 + e];
            if (h2 == 0) sh_src[e] = s;
            sh_alpha[e * HH + h2] =
                __expf(lrelu02(ssrc[s * HH + h2] + sh_sdst[h2]) - sh_m[h2]) * sh_sinv[h2];
        }
        __syncthreads();
        int e = 0;
        for (; e + 1 < cnt; e += 2) {
            float a0 = sh_alpha[e * HH + hh];
            float a1 = sh_alpha[(e + 1) * HH + hh];
            float4 v0 = *(const float4*)(hbuf + (size_t)sh_src[e] * HC + hh * CC + c4);
            float4 v1 = *(const float4*)(hbuf + (size_t)sh_src[e + 1] * HC + hh * CC + c4);
            acc.x = fmaf(a0, v0.x, fmaf(a1, v1.x, acc.x));
            acc.y = fmaf(a0, v0.y, fmaf(a1, v1.y, acc.y));
            acc.z = fmaf(a0, v0.z, fmaf(a1, v1.z, acc.z));
            acc.w = fmaf(a0, v0.w, fmaf(a1, v1.w, acc.w));
        }
        if (e < cnt) {
            float a0 = sh_alpha[e * HH + hh];
            float4 v0 = *(const float4*)(hbuf + (size_t)sh_src[e] * HC + hh * CC + c4);
            acc.x = fmaf(a0, v0.x, acc.x);
            acc.y = fmaf(a0, v0.y, acc.y);
            acc.z = fmaf(a0, v0.z, acc.z);
            acc.w = fmaf(a0, v0.w, acc.w);
        }
        __syncthreads();
    }
    float4 bb = *(const float4*)(bias + hh * CC + c4);
    acc.x += bb.x; acc.y += bb.y; acc.z += bb.z; acc.w += bb.w;
    *(float4*)(out + (size_t)dstn * HC + hh * CC + c4) = acc;
}

// ---------------- GAT aggregation, H=1 C=64, shared-alpha ----------------
__global__ void k_agg1(const float* __restrict__ h3, const float* __restrict__ ssrc,
                       const float* __restrict__ sdst, const float* __restrict__ bias,
                       float* __restrict__ out) {
    int dstn = blockIdx.x;
    int tid = threadIdx.x;
    __shared__ float sh_m, sh_sinv;
    __shared__ float sh_alpha[64];
    __shared__ int   sh_src[64];
    float sd = sdst[dstn];
    int beg = g_rowptr[dstn], end = g_rowptr[dstn + 1];
    if (tid < 32) {
        float mx = -3.4e38f;
        for (int i = beg + tid; i < end; i += 32)
            mx = fmaxf(mx, lrelu02(ssrc[g_csrc[i]] + sd));
#pragma unroll
        for (int o = 1; o < 32; o <<= 1) mx = fmaxf(mx, __shfl_xor_sync(0xffffffffu, mx, o));
        float se = 0.f;
        for (int i = beg + tid; i < end; i += 32)
            se += __expf(lrelu02(ssrc[g_csrc[i]] + sd) - mx);
#pragma unroll
        for (int o = 1; o < 32; o <<= 1) se += __shfl_xor_sync(0xffffffffu, se, o);
        if (tid == 0) { sh_m = mx; sh_sinv = 1.f / (se + 1e-16f); }
    }
    __syncthreads();
    float m = sh_m, sinv = sh_sinv;
    float acc = 0.f;
    for (int c0 = beg; c0 < end; c0 += 64) {
        int cnt = min(64, end - c0);
        if (tid < cnt) {
            int s = g_csrc[c0 + tid];
            sh_src[tid] = s;
            sh_alpha[tid] = __expf(lrelu02(ssrc[s] + sd) - m) * sinv;
        }
        __syncthreads();
        int e = 0;
        for (; e + 1 < cnt; e += 2) {
            float a0 = sh_alpha[e], a1 = sh_alpha[e + 1];
            float v0 = h3[(size_t)sh_src[e] * CC + tid];
            float v1 = h3[(size_t)sh_src[e + 1] * CC + tid];
            acc = fmaf(a0, v0, fmaf(a1, v1, acc));
        }
        if (e < cnt)
            acc = fmaf(sh_alpha[e], h3[(size_t)sh_src[e] * CC + tid], acc);
        __syncthreads();
    }
    out[(size_t)dstn * CC + tid] = acc + bias[tid];
}

// ---------------- BatchNorm stats + finalize fused (last-block pattern) ----------------
__global__ void k_bn(const float* __restrict__ x, const float* __restrict__ g,
                     const float* __restrict__ be, int Cdim, int rowsPerBlock) {
    int c = threadIdx.x;
    int b = blockIdx.x;
    int r0 = b * rowsPerBlock;
    int r1 = min(r0 + rowsPerBlock, NN);
    float s = 0.f, q = 0.f;
    for (int r = r0; r < r1; r++) {
        float v = x[(size_t)r * Cdim + c];
        s += v; q = fmaf(v, v, q);
    }
    g_bnpart[b * Cdim + c] = s;
    g_bnpart2[b * Cdim + c] = q;
    __threadfence();
    __shared__ int sh_last;
    if (c == 0) {
        int old = atomicAdd(&g_bncnt, 1);
        sh_last = (old == NBN - 1) ? 1 : 0;
    }
    __syncthreads();
    if (sh_last) {
        float ts = 0.f, tq = 0.f;
        for (int bb = 0; bb < NBN; bb++) {
            ts += g_bnpart[bb * Cdim + c];
            tq += g_bnpart2[bb * Cdim + c];
        }
        float mu = ts / (float)NN;
        float var = tq / (float)NN - mu * mu;
        var = fmaxf(var, 0.f);
        float inv = rsqrtf(var + 1e-5f);
        float sc = g[c] * inv;
        g_scale[c] = sc;
        g_shift[c] = be[c] - sc * mu;
        if (c == 0) g_bncnt = 0;     // self-reset for next use
    }
}

// out = res + elu(scale*in+shift); optional bf16 split; optional score-buffer zeroing
__global__ void k_bnapply(const float* __restrict__ in, const float* __restrict__ res,
                          float* __restrict__ out,
                          __nv_bfloat16* __restrict__ outH, __nv_bfloat16* __restrict__ outL,
                          int Cdim, int doElu, int total4, int zeroScores) {
    int i0 = blockIdx.x * blockDim.x + threadIdx.x;
    int stride = gridDim.x * blockDim.x;
    if (zeroScores) {
        for (int zi = i0; zi < NN * HH; zi += stride) { g_ssrc[zi] = 0.f; g_sdst[zi] = 0.f; }
    }
    int c4cnt = Cdim >> 2;
    for (int i = i0; i < total4; i += stride) {
        int c4 = (i % c4cnt) << 2;
        float4 v = ((const float4*)in)[i];
        float4 sc = *(const float4*)&g_scale[c4];
        float4 sh = *(const float4*)&g_shift[c4];
        float o0 = fmaf(sc.x, v.x, sh.x);
        float o1 = fmaf(sc.y, v.y, sh.y);
        float o2 = fmaf(sc.z, v.z, sh.z);
        float o3 = fmaf(sc.w, v.w, sh.w);
        if (doElu) {
            o0 = o0 > 0.f ? o0 : expm1f(o0);
            o1 = o1 > 0.f ? o1 : expm1f(o1);
            o2 = o2 > 0.f ? o2 : expm1f(o2);
            o3 = o3 > 0.f ? o3 : expm1f(o3);
        }
        if (res) {
            float4 rv = ((const float4*)res)[i];
            o0 += rv.x; o1 += rv.y; o2 += rv.z; o3 += rv.w;
        }
        ((float4*)out)[i] = make_float4(o0, o1, o2, o3);
        if (outH) {
            __nv_bfloat16 h0, h1, h2, h3, l0, l1, l2, l3;
            split_bf16(o0, h0, l0); split_bf16(o1, h1, l1);
            split_bf16(o2, h2, l2); split_bf16(o3, h3, l3);
            ((__nv_bfloat162*)outH)[2 * i]     = __halves2bfloat162(h0, h1);
            ((__nv_bfloat162*)outH)[2 * i + 1] = __halves2bfloat162(h2, h3);
            ((__nv_bfloat162*)outL)[2 * i]     = __halves2bfloat162(l0, l1);
            ((__nv_bfloat162*)outL)[2 * i + 1] = __halves2bfloat162(l2, l3);
        }
    }
}

// ---------------- fused pool + classifier (batch is sorted) ----------------
__global__ void k_poolfinal(const float* __restrict__ x3, const int* __restrict__ batch,
                            const float* __restrict__ linW, const float* __restrict__ linb,
                            float* __restrict__ out) {
    int g = blockIdx.x;
    int j = threadIdx.x;
    __shared__ float xg[CC];
    int lo = 0, hi = NN;
    while (lo < hi) { int mid = (lo + hi) >> 1; if (batch[mid] < g) lo = mid + 1; else hi = mid; }
    int beg = lo;
    hi = NN;
    while (lo < hi) { int mid = (lo + hi) >> 1; if (batch[mid] <= g) lo = mid + 1; else hi = mid; }
    int end = lo;
    float s = 0.f;
    for (int n = beg; n < end; n++) s += x3[(size_t)n * CC + j];
    float cv = fmaxf((float)(end - beg), 1.0f);
    xg[j] = s / cv;
    __syncthreads();
    float acc = linb[j];
#pragma unroll
    for (int c = 0; c < CC; c++) acc = fmaf(xg[c], linW[c * NCLS + j], acc);
    out[g * NCLS + j] = acc;
}

// ---------------- host side ----------------
extern "C" void kernel_launch(void* const* d_in, const int* in_sizes, int n_in,
                              void* d_out, int out_size) {
    const float* x      = (const float*)d_in[0];
    const int*   ei     = (const int*)d_in[1];
    const int*   batch  = (const int*)d_in[2];
    const float* enc_W  = (const float*)d_in[3];
    const float* enc_b  = (const float*)d_in[4];
    const float* W1     = (const float*)d_in[5];
    const float* as1    = (const float*)d_in[6];
    const float* ad1    = (const float*)d_in[7];
    const float* b1     = (const float*)d_in[8];
    const float* g1     = (const float*)d_in[9];
    const float* be1    = (const float*)d_in[10];
    const float* W2     = (const float*)d_in[11];
    const float* as2    = (const float*)d_in[12];
    const float* ad2    = (const float*)d_in[13];
    const float* b2     = (const float*)d_in[14];
    const float* g2     = (const float*)d_in[15];
    const float* be2    = (const float*)d_in[16];
    const float* W3     = (const float*)d_in[17];
    const float* as3    = (const float*)d_in[18];
    const float* ad3    = (const float*)d_in[19];
    const float* b3     = (const float*)d_in[20];
    const float* g3     = (const float*)d_in[21];
    const float* be3    = (const float*)d_in[22];
    const float* linW   = (const float*)d_in[23];
    const float* linb   = (const float*)d_in[24];
    float* out = (float*)d_out;

    float *bufA, *bufB, *hbuf, *gat, *ssrc, *sdst, *x3, *gat3;
    __nv_bfloat16 *Ah, *Al, *Ah2, *Al2, *Wth, *Wtl;
    cudaGetSymbolAddress((void**)&bufA, g_bufA);
    cudaGetSymbolAddress((void**)&bufB, g_bufB);
    cudaGetSymbolAddress((void**)&hbuf, g_h);
    cudaGetSymbolAddress((void**)&gat,  g_gat);
    cudaGetSymbolAddress((void**)&ssrc, g_ssrc);
    cudaGetSymbolAddress((void**)&sdst, g_sdst);
    cudaGetSymbolAddress((void**)&x3,   g_x3);
    cudaGetSymbolAddress((void**)&gat3, g_gat3);
    cudaGetSymbolAddress((void**)&Ah,   g_Ah);
    cudaGetSymbolAddress((void**)&Al,   g_Al);
    cudaGetSymbolAddress((void**)&Ah2,  g_Ah2);
    cudaGetSymbolAddress((void**)&Al2,  g_Al2);
    cudaGetSymbolAddress((void**)&Wth,  g_WthA);
    cudaGetSymbolAddress((void**)&Wtl,  g_WtlA);
    __nv_bfloat16 *Wth0 = Wth,              *Wtl0 = Wtl;
    __nv_bfloat16 *Wth1 = Wth + HC * HC,    *Wtl1 = Wtl + HC * HC;
    __nv_bfloat16 *Wth2 = Wth + 2 * HC * HC,*Wtl2 = Wtl + 2 * HC * HC;
    __nv_bfloat16 *Wth3 = Wth + 3 * HC * HC,*Wtl3 = Wtl + 3 * HC * HC;

    cudaFuncSetAttribute(k_gemm_mma, cudaFuncAttributeMaxDynamicSharedMemorySize, SMEM_GEMM);

    dim3 gGrid(HC / 64, (NN + 127) / 128);
    dim3 gGrid3(1, (NN + 127) / 128);
    const int T4 = NN * HC / 4;
    const int T4c = NN * CC / 4;

    // launch 0: prep; 1: count; 2: scan+fillself; 3: encoder GEMM (ncu slot)
    k_prep<<<dim3(16, 16, 6), dim3(32, 8)>>>(x, Ah, Al, enc_W, W1, W2, W3);
    k_count<<<(EE + 255) / 256, 256>>>(ei);
    k_scanfill<<<1, 1024>>>();
    k_gemm_mma<<<gGrid, 256, SMEM_GEMM>>>(Ah, Al, Wth0, Wtl0, enc_b, bufA, Ah2, Al2,
                                          nullptr, nullptr, HH, NN, HC);
    k_fill<<<(EE + 255) / 256, 256>>>(ei);

    // ---- layer 1 ----
    k_gemm_mma<<<gGrid, 256, SMEM_GEMM>>>(Ah2, Al2, Wth1, Wtl1, nullptr, hbuf, nullptr, nullptr,
                                          as1, ad1, HH, NN, HC);
    k_agg8<<<NN, 128>>>(hbuf, ssrc, sdst, b1, gat);
    k_bn<<<NBN, HC>>>(gat, g1, be1, HC, NN / NBN);
    k_bnapply<<<512, 256>>>(gat, bufA, bufB, Ah, Al, HC, 1, T4, 1);

    // ---- layer 2 ----
    k_gemm_mma<<<gGrid, 256, SMEM_GEMM>>>(Ah, Al, Wth2, Wtl2, nullptr, hbuf, nullptr, nullptr,
                                          as2, ad2, HH, NN, HC);
    k_agg8<<<NN, 128>>>(hbuf, ssrc, sdst, b2, gat);
    k_bn<<<NBN, HC>>>(gat, g2, be2, HC, NN / NBN);
    k_bnapply<<<512, 256>>>(gat, bufB, bufA, Ah2, Al2, HC, 1, T4, 1);

    // ---- layer 3 (H=1) ----
    k_gemm_mma<<<gGrid3, 256, SMEM_GEMM>>>(Ah2, Al2, Wth3, Wtl3, nullptr, x3, nullptr, nullptr,
                                           as3, ad3, 1, NN, CC);
    k_agg1<<<NN, 64>>>(x3, ssrc, sdst, b3, gat3);
    k_bn<<<NBN, CC>>>(gat3, g3, be3, CC, NN / NBN);
    k_bnapply<<<256, 256>>>(gat3, nullptr, x3, nullptr, nullptr, CC, 0, T4c, 0);

    // ---- fused pool + classifier ----
    k_poolfinal<<<GG, NCLS>>>(x3, batch, linW, linb, out);
}